// round 1
// baseline (speedup 1.0000x reference)
#include <cuda_runtime.h>
#include <cuda_bf16.h>
#include <cstddef>

// ---------------------------------------------------------------------------
// Scratch buffers (no cudaMalloc allowed): ping-pong through device globals.
//   bufA: up to 2*64*1024*1024 floats (512 MB)  -- largest intermediate (z2)
//   bufB: up to 2*32*1024*1024 floats (256 MB)
//   g_h : shuffled image, 2*1*1024*1024 floats (8 MB), live until the end
// ---------------------------------------------------------------------------
__device__ float g_bufA[134217728];
__device__ float g_bufB[67108864];
__device__ float g_h[2097152];

// ---------------------------------------------------------------------------
// Generic 3x3 SAME conv + ReLU, NCHW, OIHW weights.
//   block: 256 threads = (32 cols) x (8 rows), each thread computes PX rows
//   tile : 32 x (8*PX) outputs, CO_T output channels per block (in registers)
//   grid : (W/32, H/(8*PX), N * CO/CO_T)
// ---------------------------------------------------------------------------
template <int CI, int COT, int PX>
__global__ __launch_bounds__(256)
void conv3x3_relu_k(const float* __restrict__ in, const float* __restrict__ w,
                    float* __restrict__ out, int H, int W, int CO)
{
    constexpr int TW = 32;
    constexpr int TH = 8 * PX;
    __shared__ float st[(TH + 2) * (TW + 2)];
    __shared__ float ws[COT * CI * 9];

    const int tid = threadIdx.x;
    const int tx = tid & 31;
    const int ty = tid >> 5;

    const int groups = CO / COT;
    const int g  = blockIdx.z % groups;
    const int n  = blockIdx.z / groups;
    const int co0 = g * COT;

    // Weights for [co0, co0+COT) are contiguous in OIHW.
    for (int i = tid; i < COT * CI * 9; i += 256)
        ws[i] = w[co0 * CI * 9 + i];

    const int gx0 = blockIdx.x * TW;
    const int gy0 = blockIdx.y * TH;

    float acc[PX][COT];
#pragma unroll
    for (int p = 0; p < PX; ++p)
#pragma unroll
        for (int c = 0; c < COT; ++c) acc[p][c] = 0.f;

    const float* inN = in + (size_t)n * CI * H * W;
    const int r0 = ty * PX;

    for (int ci = 0; ci < CI; ++ci) {
        __syncthreads();  // also covers the weight load on the first iteration
        const float* ip = inN + (size_t)ci * H * W;
        for (int i = tid; i < (TH + 2) * (TW + 2); i += 256) {
            int r = i / (TW + 2), c = i % (TW + 2);
            int gy = gy0 + r - 1, gx = gx0 + c - 1;
            st[i] = (gy >= 0 && gy < H && gx >= 0 && gx < W) ? ip[gy * W + gx] : 0.f;
        }
        __syncthreads();

        // Cache this thread's (PX+2) x 3 input neighborhood in registers.
        float v[PX + 2][3];
#pragma unroll
        for (int dy = 0; dy < PX + 2; ++dy)
#pragma unroll
            for (int dx = 0; dx < 3; ++dx)
                v[dy][dx] = st[(r0 + dy) * (TW + 2) + tx + dx];

        const float* wci = ws + ci * 9;
#pragma unroll
        for (int c = 0; c < COT; ++c) {
            const float* wp = wci + c * CI * 9;
#pragma unroll
            for (int kh = 0; kh < 3; ++kh)
#pragma unroll
                for (int kw = 0; kw < 3; ++kw) {
                    float wv = wp[kh * 3 + kw];
#pragma unroll
                    for (int p = 0; p < PX; ++p)
                        acc[p][c] += v[p + kh][kw] * wv;
                }
        }
    }

#pragma unroll
    for (int c = 0; c < COT; ++c) {
        float* op = out + ((size_t)(n * CO + co0 + c) * H + gy0 + r0) * W + gx0 + tx;
#pragma unroll
        for (int p = 0; p < PX; ++p) {
            float vv = acc[p][c];
            op[(size_t)p * W] = vv > 0.f ? vv : 0.f;
        }
    }
}

// ---------------------------------------------------------------------------
// PixelShuffle(4) + ReLU: (2,16,256,256) -> (2,1,1024,1024)
// out[n, y, x] = relu(in[n, (y%4)*4 + (x%4), y/4, x/4])
// ---------------------------------------------------------------------------
__global__ void shuffle_relu_k(const float* __restrict__ in, float* __restrict__ out)
{
    int idx = blockIdx.x * blockDim.x + threadIdx.x;  // 0 .. 2*1024*1024-1
    int x = idx & 1023;
    int y = (idx >> 10) & 1023;
    int n = idx >> 20;
    int c = ((y & 3) << 2) | (x & 3);
    int hh = y >> 2, ww = x >> 2;
    float v = in[(((size_t)(n * 16 + c) * 256) + hh) * 256 + ww];
    out[idx] = v > 0.f ? v : 0.f;
}

// ---------------------------------------------------------------------------
// Per-pixel 5x5 dynamic conv + residual: out = h + sum_{kw,kh} h_pad * ker
// h: (N,1,1024,1024); ker: (N,25,1024,1024) with channel j = kw*5 + kh
// block 256 = (32,8), each thread 4 rows; tile 32x32 with halo 2 in smem.
// ---------------------------------------------------------------------------
__global__ __launch_bounds__(256)
void pixel_conv_add_k(const float* __restrict__ h, const float* __restrict__ ker,
                      float* __restrict__ out)
{
    constexpr int H = 1024, W = 1024;
    __shared__ float st[36 * 36];
    const int tid = threadIdx.x;
    const int tx = tid & 31, ty = tid >> 5;
    const int n = blockIdx.z;
    const int gx0 = blockIdx.x * 32, gy0 = blockIdx.y * 32;

    const float* hp = h + (size_t)n * H * W;
    for (int i = tid; i < 36 * 36; i += 256) {
        int r = i / 36, c = i % 36;
        int gy = gy0 + r - 2, gx = gx0 + c - 2;
        st[i] = (gy >= 0 && gy < H && gx >= 0 && gx < W) ? hp[gy * W + gx] : 0.f;
    }
    __syncthreads();

    const int r0 = ty * 4;
    const int x = gx0 + tx;
    float acc[4];
#pragma unroll
    for (int p = 0; p < 4; ++p)
        acc[p] = st[(r0 + p + 2) * 36 + tx + 2];  // residual h

#pragma unroll
    for (int kw = 0; kw < 5; ++kw)
#pragma unroll
        for (int kh = 0; kh < 5; ++kh) {
            const int j = kw * 5 + kh;
            const float* kp = ker + ((size_t)(n * 25 + j) * H + gy0 + r0) * W + x;
#pragma unroll
            for (int p = 0; p < 4; ++p) {
                float kv = kp[(size_t)p * W];
                acc[p] += st[(r0 + p + kh) * 36 + tx + kw] * kv;
            }
        }

#pragma unroll
    for (int p = 0; p < 4; ++p)
        out[((size_t)n * H + gy0 + r0 + p) * W + x] = acc[p];
}

// ---------------------------------------------------------------------------
// Launch sequence (graph-capturable: kernel launches only)
// ---------------------------------------------------------------------------
extern "C" void kernel_launch(void* const* d_in, const int* in_sizes, int n_in,
                              void* d_out, int out_size)
{
    const float* x   = (const float*)d_in[0];
    const float* we1 = (const float*)d_in[1];
    const float* we2 = (const float*)d_in[2];
    const float* we3 = (const float*)d_in[3];
    const float* wd1 = (const float*)d_in[4];
    const float* wd2 = (const float*)d_in[5];
    const float* wk1 = (const float*)d_in[6];
    const float* wk2 = (const float*)d_in[7];
    const float* wk3 = (const float*)d_in[8];
    const float* wk4 = (const float*)d_in[9];
    float* out = (float*)d_out;

    float *bufA, *bufB, *hbuf;
    cudaGetSymbolAddress((void**)&bufA, g_bufA);
    cudaGetSymbolAddress((void**)&bufB, g_bufB);
    cudaGetSymbolAddress((void**)&hbuf, g_h);

    const dim3 blk(256);

    // encoder / decoder @ 256x256 (N=2)
    conv3x3_relu_k<1, 16, 4><<<dim3(8, 8, 2), blk>>>(x,    we1, bufA, 256, 256, 16);
    conv3x3_relu_k<16, 16, 4><<<dim3(8, 8, 4), blk>>>(bufA, we2, bufB, 256, 256, 32);
    conv3x3_relu_k<32, 16, 4><<<dim3(8, 8, 8), blk>>>(bufB, we3, bufA, 256, 256, 64);
    conv3x3_relu_k<64, 16, 4><<<dim3(8, 8, 4), blk>>>(bufA, wd1, bufB, 256, 256, 32);
    conv3x3_relu_k<32, 16, 4><<<dim3(8, 8, 2), blk>>>(bufB, wd2, bufA, 256, 256, 16);

    // pixel shuffle + relu -> (2,1,1024,1024)
    shuffle_relu_k<<<8192, 256>>>(bufA, hbuf);

    // kernel-prediction branch @ 1024x1024
    conv3x3_relu_k<1, 16, 4><<<dim3(32, 32, 4), blk>>>(hbuf, wk1, bufB, 1024, 1024, 32);
    conv3x3_relu_k<32, 16, 4><<<dim3(32, 32, 8), blk>>>(bufB, wk2, bufA, 1024, 1024, 64);
    conv3x3_relu_k<64, 16, 4><<<dim3(32, 32, 4), blk>>>(bufA, wk3, bufB, 1024, 1024, 32);
    conv3x3_relu_k<32, 25, 2><<<dim3(32, 64, 2), blk>>>(bufB, wk4, bufA, 1024, 1024, 25);

    // per-pixel 5x5 conv + residual add
    pixel_conv_add_k<<<dim3(32, 32, 2), blk>>>(hbuf, bufA, out);
}

// round 2
// speedup vs baseline: 1.0139x; 1.0139x over previous
#include <cuda_runtime.h>
#include <cuda_bf16.h>
#include <cstddef>

// ---------------------------------------------------------------------------
// Scratch buffers (no cudaMalloc allowed): ping-pong through device globals.
//   bufA: up to 2*64*1024*1024 floats (512 MB)  -- largest intermediate (z2)
//   bufB: up to 2*32*1024*1024 floats (256 MB)
//   g_h : shuffled image, 2*1*1024*1024 floats (8 MB), live until the end
// ---------------------------------------------------------------------------
__device__ float g_bufA[134217728];
__device__ float g_bufB[67108864];
__device__ float g_h[2097152];

// ---------------------------------------------------------------------------
// Generic 3x3 SAME conv + ReLU, NCHW, OIHW weights.
//   block: 256 threads = (32 cols) x (8 rows), each thread computes PX rows
//   tile : 32 x (8*PX) outputs, CO_T output channels per block (in registers)
//   grid : (W/32, H/(8*PX), N * CO/CO_T)
// ---------------------------------------------------------------------------
template <int CI, int COT, int PX>
__global__ __launch_bounds__(256)
void conv3x3_relu_k(const float* __restrict__ in, const float* __restrict__ w,
                    float* __restrict__ out, int H, int W, int CO)
{
    constexpr int TW = 32;
    constexpr int TH = 8 * PX;
    __shared__ float st[(TH + 2) * (TW + 2)];
    __shared__ float ws[COT * CI * 9];

    const int tid = threadIdx.x;
    const int tx = tid & 31;
    const int ty = tid >> 5;

    const int groups = CO / COT;
    const int g  = blockIdx.z % groups;
    const int n  = blockIdx.z / groups;
    const int co0 = g * COT;

    // Weights for [co0, co0+COT) are contiguous in OIHW.
    for (int i = tid; i < COT * CI * 9; i += 256)
        ws[i] = w[co0 * CI * 9 + i];

    const int gx0 = blockIdx.x * TW;
    const int gy0 = blockIdx.y * TH;

    float acc[PX][COT];
#pragma unroll
    for (int p = 0; p < PX; ++p)
#pragma unroll
        for (int c = 0; c < COT; ++c) acc[p][c] = 0.f;

    const float* inN = in + (size_t)n * CI * H * W;
    const int r0 = ty * PX;

    for (int ci = 0; ci < CI; ++ci) {
        __syncthreads();  // also covers the weight load on the first iteration
        const float* ip = inN + (size_t)ci * H * W;
        for (int i = tid; i < (TH + 2) * (TW + 2); i += 256) {
            int r = i / (TW + 2), c = i % (TW + 2);
            int gy = gy0 + r - 1, gx = gx0 + c - 1;
            st[i] = (gy >= 0 && gy < H && gx >= 0 && gx < W) ? ip[gy * W + gx] : 0.f;
        }
        __syncthreads();

        // Cache this thread's (PX+2) x 3 input neighborhood in registers.
        float v[PX + 2][3];
#pragma unroll
        for (int dy = 0; dy < PX + 2; ++dy)
#pragma unroll
            for (int dx = 0; dx < 3; ++dx)
                v[dy][dx] = st[(r0 + dy) * (TW + 2) + tx + dx];

        const float* wci = ws + ci * 9;
#pragma unroll
        for (int c = 0; c < COT; ++c) {
            const float* wp = wci + c * CI * 9;
#pragma unroll
            for (int kh = 0; kh < 3; ++kh)
#pragma unroll
                for (int kw = 0; kw < 3; ++kw) {
                    float wv = wp[kh * 3 + kw];
#pragma unroll
                    for (int p = 0; p < PX; ++p)
                        acc[p][c] += v[p + kh][kw] * wv;
                }
        }
    }

#pragma unroll
    for (int c = 0; c < COT; ++c) {
        float* op = out + ((size_t)(n * CO + co0 + c) * H + gy0 + r0) * W + gx0 + tx;
#pragma unroll
        for (int p = 0; p < PX; ++p) {
            float vv = acc[p][c];
            op[(size_t)p * W] = vv > 0.f ? vv : 0.f;
        }
    }
}

// ---------------------------------------------------------------------------
// PixelShuffle(4) + ReLU: (2,16,256,256) -> (2,1,1024,1024)
// out[n, y, x] = relu(in[n, (y%4)*4 + (x%4), y/4, x/4])
// ---------------------------------------------------------------------------
__global__ void shuffle_relu_k(const float* __restrict__ in, float* __restrict__ out)
{
    int idx = blockIdx.x * blockDim.x + threadIdx.x;  // 0 .. 2*1024*1024-1
    int x = idx & 1023;
    int y = (idx >> 10) & 1023;
    int n = idx >> 20;
    int c = ((y & 3) << 2) | (x & 3);
    int hh = y >> 2, ww = x >> 2;
    float v = in[(((size_t)(n * 16 + c) * 256) + hh) * 256 + ww];
    out[idx] = v > 0.f ? v : 0.f;
}

// ---------------------------------------------------------------------------
// Per-pixel 5x5 dynamic conv + residual: out = h + sum_{kw,kh} h_pad * ker
// h: (N,1,1024,1024); ker: (N,25,1024,1024) with channel j = kw*5 + kh
// block 256 = (32,8), each thread 4 rows; tile 32x32 with halo 2 in smem.
// ---------------------------------------------------------------------------
__global__ __launch_bounds__(256)
void pixel_conv_add_k(const float* __restrict__ h, const float* __restrict__ ker,
                      float* __restrict__ out)
{
    constexpr int H = 1024, W = 1024;
    __shared__ float st[36 * 36];
    const int tid = threadIdx.x;
    const int tx = tid & 31, ty = tid >> 5;
    const int n = blockIdx.z;
    const int gx0 = blockIdx.x * 32, gy0 = blockIdx.y * 32;

    const float* hp = h + (size_t)n * H * W;
    for (int i = tid; i < 36 * 36; i += 256) {
        int r = i / 36, c = i % 36;
        int gy = gy0 + r - 2, gx = gx0 + c - 2;
        st[i] = (gy >= 0 && gy < H && gx >= 0 && gx < W) ? hp[gy * W + gx] : 0.f;
    }
    __syncthreads();

    const int r0 = ty * 4;
    const int x = gx0 + tx;
    float acc[4];
#pragma unroll
    for (int p = 0; p < 4; ++p)
        acc[p] = st[(r0 + p + 2) * 36 + tx + 2];  // residual h

#pragma unroll
    for (int kw = 0; kw < 5; ++kw)
#pragma unroll
        for (int kh = 0; kh < 5; ++kh) {
            const int j = kw * 5 + kh;
            const float* kp = ker + ((size_t)(n * 25 + j) * H + gy0 + r0) * W + x;
#pragma unroll
            for (int p = 0; p < 4; ++p) {
                float kv = kp[(size_t)p * W];
                acc[p] += st[(r0 + p + kh) * 36 + tx + kw] * kv;
            }
        }

#pragma unroll
    for (int p = 0; p < 4; ++p)
        out[((size_t)n * H + gy0 + r0 + p) * W + x] = acc[p];
}

// ---------------------------------------------------------------------------
// Launch sequence (graph-capturable: kernel launches only)
// ---------------------------------------------------------------------------
extern "C" void kernel_launch(void* const* d_in, const int* in_sizes, int n_in,
                              void* d_out, int out_size)
{
    const float* x   = (const float*)d_in[0];
    const float* we1 = (const float*)d_in[1];
    const float* we2 = (const float*)d_in[2];
    const float* we3 = (const float*)d_in[3];
    const float* wd1 = (const float*)d_in[4];
    const float* wd2 = (const float*)d_in[5];
    const float* wk1 = (const float*)d_in[6];
    const float* wk2 = (const float*)d_in[7];
    const float* wk3 = (const float*)d_in[8];
    const float* wk4 = (const float*)d_in[9];
    float* out = (float*)d_out;

    float *bufA, *bufB, *hbuf;
    cudaGetSymbolAddress((void**)&bufA, g_bufA);
    cudaGetSymbolAddress((void**)&bufB, g_bufB);
    cudaGetSymbolAddress((void**)&hbuf, g_h);

    const dim3 blk(256);

    // encoder / decoder @ 256x256 (N=2)
    conv3x3_relu_k<1, 16, 4><<<dim3(8, 8, 2), blk>>>(x,    we1, bufA, 256, 256, 16);
    conv3x3_relu_k<16, 16, 4><<<dim3(8, 8, 4), blk>>>(bufA, we2, bufB, 256, 256, 32);
    conv3x3_relu_k<32, 16, 4><<<dim3(8, 8, 8), blk>>>(bufB, we3, bufA, 256, 256, 64);
    conv3x3_relu_k<64, 16, 4><<<dim3(8, 8, 4), blk>>>(bufA, wd1, bufB, 256, 256, 32);
    conv3x3_relu_k<32, 16, 4><<<dim3(8, 8, 2), blk>>>(bufB, wd2, bufA, 256, 256, 16);

    // pixel shuffle + relu -> (2,1,1024,1024)
    shuffle_relu_k<<<8192, 256>>>(bufA, hbuf);

    // kernel-prediction branch @ 1024x1024
    conv3x3_relu_k<1, 16, 4><<<dim3(32, 32, 4), blk>>>(hbuf, wk1, bufB, 1024, 1024, 32);
    conv3x3_relu_k<32, 16, 4><<<dim3(32, 32, 8), blk>>>(bufB, wk2, bufA, 1024, 1024, 64);
    conv3x3_relu_k<64, 16, 4><<<dim3(32, 32, 4), blk>>>(bufA, wk3, bufB, 1024, 1024, 32);
    conv3x3_relu_k<32, 25, 2><<<dim3(32, 64, 2), blk>>>(bufB, wk4, bufA, 1024, 1024, 25);

    // per-pixel 5x5 conv + residual add
    pixel_conv_add_k<<<dim3(32, 32, 2), blk>>>(hbuf, bufA, out);
}

// round 3
// speedup vs baseline: 2.5920x; 2.5564x over previous
#include <cuda_runtime.h>
#include <cuda_bf16.h>
#include <cstddef>

// ---------------------------------------------------------------------------
// Scratch buffers (no cudaMalloc allowed): ping-pong through device globals.
// ---------------------------------------------------------------------------
__device__ float g_bufA[134217728];   // 512 MB : largest intermediate (64ch @1024^2 x2)
__device__ float g_bufB[67108864];    // 256 MB
__device__ float g_h[2097152];        // 8 MB : shuffled image

// ---------------------------------------------------------------------------
// TF32 helpers
// ---------------------------------------------------------------------------
__device__ __forceinline__ unsigned f2tf32(float f) {
    unsigned r;
    asm("cvt.rna.tf32.f32 %0, %1;" : "=r"(r) : "f"(f));
    return r;
}

__device__ __forceinline__ void mma_tf32(float* c,
                                         unsigned a0, unsigned a1, unsigned a2, unsigned a3,
                                         unsigned b0, unsigned b1) {
    asm volatile("mma.sync.aligned.m16n8k8.row.col.f32.tf32.tf32.f32 "
                 "{%0,%1,%2,%3}, {%4,%5,%6,%7}, {%8,%9}, {%0,%1,%2,%3};"
                 : "+f"(c[0]), "+f"(c[1]), "+f"(c[2]), "+f"(c[3])
                 : "r"(a0), "r"(a1), "r"(a2), "r"(a3), "r"(b0), "r"(b1));
}

// ---------------------------------------------------------------------------
// TF32 tensor-core 3x3 SAME conv + ReLU for 1024x1024 images, NCHW / OIHW.
//   Block: 256 threads (8 warps). Pixel tile 32(x) x 8(y); warp w owns row w.
//   Each warp: 2 M-tiles (16 px each) x NT N-tiles (8 co each), K = CI*9 via
//   9 taps x (CI/8) k-steps of m16n8k8 tf32 mma.
//   Input tile in smem (tf32-rounded, pitch 36 -> conflict-free A loads).
//   Weights prepacked in smem as per-lane B fragments (float2, conflict-free).
//   COP = CO padded to multiple of 8; COR = real CO (store-masked).
// ---------------------------------------------------------------------------
template <int CI, int COP, int COR>
__global__ __launch_bounds__(256, 1)
void conv3x3_tf32_k(const float* __restrict__ in, const float* __restrict__ w,
                    float* __restrict__ out)
{
    constexpr int H = 1024, W = 1024;
    constexpr int KS = CI / 8;        // k-steps
    constexpr int NT = COP / 8;       // n-tiles
    constexpr int IPITCH = 36;        // smem row pitch (floats); 10*36 mod 32 = 8
    constexpr int ICH = 10 * IPITCH;  // floats per channel slice

    extern __shared__ unsigned smem_u[];
    unsigned* in_s = smem_u;                          // CI * ICH
    uint2*    ws   = (uint2*)(smem_u + CI * ICH);     // 9*KS*NT*32 fragments

    const int tid  = threadIdx.x;
    const int lane = tid & 31;
    const int wrp  = tid >> 5;
    const int gx0  = blockIdx.x * 32;
    const int gy0  = blockIdx.y * 8;
    const int img  = blockIdx.z;

    // ---- weight prepack: B fragment for (tap t, kstep k, ntile n, lane) ----
    for (int i = tid; i < 9 * KS * NT * 32; i += 256) {
        int l = i & 31, r = i >> 5;
        int n = r % NT; r /= NT;
        int k = r % KS; int t = r / KS;
        int co = n * 8 + (l >> 2);
        int ci = k * 8 + (l & 3);
        float b0 = 0.f, b1 = 0.f;
        if (co < COR) {
            b0 = w[(co * CI + ci) * 9 + t];
            b1 = w[(co * CI + ci + 4) * 9 + t];
        }
        ws[i] = make_uint2(f2tf32(b0), f2tf32(b1));
    }

    // ---- input tile with halo (rows gy0-1..gy0+8, cols gx0-1..gx0+32) ----
    const float* inN = in + (size_t)img * CI * H * W;
    for (int i = tid; i < CI * 340; i += 256) {
        int ci = i / 340, rem = i % 340;
        int r = rem / 34, c = rem % 34;
        int gy = gy0 + r - 1, gx = gx0 + c - 1;
        float v = 0.f;
        if (gy >= 0 && gy < H && gx >= 0 && gx < W)
            v = inN[(size_t)ci * H * W + gy * W + gx];
        in_s[ci * ICH + r * IPITCH + c] = f2tf32(v);
    }
    __syncthreads();

    float acc[2][NT][4];
#pragma unroll
    for (int m = 0; m < 2; ++m)
#pragma unroll
        for (int n = 0; n < NT; ++n)
#pragma unroll
            for (int i = 0; i < 4; ++i) acc[m][n][i] = 0.f;

    const int arow = lane >> 2;   // pixel offset within M-tile
    const int aci  = lane & 3;    // ci offset within K-tile

#pragma unroll
    for (int kh = 0; kh < 3; ++kh) {
#pragma unroll
        for (int kw = 0; kw < 3; ++kw) {
            const int t = kh * 3 + kw;
            const int roff = (wrp + kh) * IPITCH + kw + arow;
            const uint2* wb = ws + (size_t)t * KS * NT * 32 + lane;
#pragma unroll
            for (int k = 0; k < KS; ++k) {
                const int ab = (k * 8 + aci) * ICH + roff;
                unsigned a00 = in_s[ab];
                unsigned a01 = in_s[ab + 8];
                unsigned a02 = in_s[ab + 4 * ICH];
                unsigned a03 = in_s[ab + 4 * ICH + 8];
                unsigned a10 = in_s[ab + 16];
                unsigned a11 = in_s[ab + 24];
                unsigned a12 = in_s[ab + 4 * ICH + 16];
                unsigned a13 = in_s[ab + 4 * ICH + 24];
#pragma unroll
                for (int n = 0; n < NT; ++n) {
                    uint2 b = wb[(k * NT + n) * 32];
                    mma_tf32(acc[0][n], a00, a01, a02, a03, b.x, b.y);
                    mma_tf32(acc[1][n], a10, a11, a12, a13, b.x, b.y);
                }
            }
        }
    }

    // ---- epilogue: ReLU + store ----
    const int y = gy0 + wrp;
#pragma unroll
    for (int m = 0; m < 2; ++m) {
        const int x0 = gx0 + m * 16 + arow;
#pragma unroll
        for (int n = 0; n < NT; ++n) {
            const int coA = n * 8 + 2 * (lane & 3);
            float v0 = fmaxf(acc[m][n][0], 0.f);
            float v1 = fmaxf(acc[m][n][1], 0.f);
            float v2 = fmaxf(acc[m][n][2], 0.f);
            float v3 = fmaxf(acc[m][n][3], 0.f);
            if (coA < COR) {
                float* p = out + ((size_t)(img * COR + coA) * H + y) * W;
                p[x0]     = v0;
                p[x0 + 8] = v2;
            }
            if (coA + 1 < COR) {
                float* p = out + ((size_t)(img * COR + coA + 1) * H + y) * W;
                p[x0]     = v1;
                p[x0 + 8] = v3;
            }
        }
    }
}

// ---------------------------------------------------------------------------
// Generic fp32 3x3 SAME conv + ReLU (used for 256^2 encoder/decoder and k1).
// ---------------------------------------------------------------------------
template <int CI, int COT, int PX>
__global__ __launch_bounds__(256)
void conv3x3_relu_k(const float* __restrict__ in, const float* __restrict__ w,
                    float* __restrict__ out, int H, int W, int CO)
{
    constexpr int TW = 32;
    constexpr int TH = 8 * PX;
    __shared__ float st[(TH + 2) * (TW + 2)];
    __shared__ float ws[COT * CI * 9];

    const int tid = threadIdx.x;
    const int tx = tid & 31;
    const int ty = tid >> 5;

    const int groups = CO / COT;
    const int g  = blockIdx.z % groups;
    const int n  = blockIdx.z / groups;
    const int co0 = g * COT;

    for (int i = tid; i < COT * CI * 9; i += 256)
        ws[i] = w[co0 * CI * 9 + i];

    const int gx0 = blockIdx.x * TW;
    const int gy0 = blockIdx.y * TH;

    float acc[PX][COT];
#pragma unroll
    for (int p = 0; p < PX; ++p)
#pragma unroll
        for (int c = 0; c < COT; ++c) acc[p][c] = 0.f;

    const float* inN = in + (size_t)n * CI * H * W;
    const int r0 = ty * PX;

    for (int ci = 0; ci < CI; ++ci) {
        __syncthreads();
        const float* ip = inN + (size_t)ci * H * W;
        for (int i = tid; i < (TH + 2) * (TW + 2); i += 256) {
            int r = i / (TW + 2), c = i % (TW + 2);
            int gy = gy0 + r - 1, gx = gx0 + c - 1;
            st[i] = (gy >= 0 && gy < H && gx >= 0 && gx < W) ? ip[gy * W + gx] : 0.f;
        }
        __syncthreads();

        float v[PX + 2][3];
#pragma unroll
        for (int dy = 0; dy < PX + 2; ++dy)
#pragma unroll
            for (int dx = 0; dx < 3; ++dx)
                v[dy][dx] = st[(r0 + dy) * (TW + 2) + tx + dx];

        const float* wci = ws + ci * 9;
#pragma unroll
        for (int c = 0; c < COT; ++c) {
            const float* wp = wci + c * CI * 9;
#pragma unroll
            for (int kh = 0; kh < 3; ++kh)
#pragma unroll
                for (int kw = 0; kw < 3; ++kw) {
                    float wv = wp[kh * 3 + kw];
#pragma unroll
                    for (int p = 0; p < PX; ++p)
                        acc[p][c] += v[p + kh][kw] * wv;
                }
        }
    }

#pragma unroll
    for (int c = 0; c < COT; ++c) {
        float* op = out + ((size_t)(n * CO + co0 + c) * H + gy0 + r0) * W + gx0 + tx;
#pragma unroll
        for (int p = 0; p < PX; ++p) {
            float vv = acc[p][c];
            op[(size_t)p * W] = vv > 0.f ? vv : 0.f;
        }
    }
}

// ---------------------------------------------------------------------------
// PixelShuffle(4) + ReLU: (2,16,256,256) -> (2,1,1024,1024)
// ---------------------------------------------------------------------------
__global__ void shuffle_relu_k(const float* __restrict__ in, float* __restrict__ out)
{
    int idx = blockIdx.x * blockDim.x + threadIdx.x;
    int x = idx & 1023;
    int y = (idx >> 10) & 1023;
    int n = idx >> 20;
    int c = ((y & 3) << 2) | (x & 3);
    int hh = y >> 2, ww = x >> 2;
    float v = in[(((size_t)(n * 16 + c) * 256) + hh) * 256 + ww];
    out[idx] = v > 0.f ? v : 0.f;
}

// ---------------------------------------------------------------------------
// Per-pixel 5x5 dynamic conv + residual add.
// ---------------------------------------------------------------------------
__global__ __launch_bounds__(256)
void pixel_conv_add_k(const float* __restrict__ h, const float* __restrict__ ker,
                      float* __restrict__ out)
{
    constexpr int H = 1024, W = 1024;
    __shared__ float st[36 * 36];
    const int tid = threadIdx.x;
    const int tx = tid & 31, ty = tid >> 5;
    const int n = blockIdx.z;
    const int gx0 = blockIdx.x * 32, gy0 = blockIdx.y * 32;

    const float* hp = h + (size_t)n * H * W;
    for (int i = tid; i < 36 * 36; i += 256) {
        int r = i / 36, c = i % 36;
        int gy = gy0 + r - 2, gx = gx0 + c - 2;
        st[i] = (gy >= 0 && gy < H && gx >= 0 && gx < W) ? hp[gy * W + gx] : 0.f;
    }
    __syncthreads();

    const int r0 = ty * 4;
    const int x = gx0 + tx;
    float acc[4];
#pragma unroll
    for (int p = 0; p < 4; ++p)
        acc[p] = st[(r0 + p + 2) * 36 + tx + 2];  // residual h

#pragma unroll
    for (int kw = 0; kw < 5; ++kw)
#pragma unroll
        for (int kh = 0; kh < 5; ++kh) {
            const int j = kw * 5 + kh;
            const float* kp = ker + ((size_t)(n * 25 + j) * H + gy0 + r0) * W + x;
#pragma unroll
            for (int p = 0; p < 4; ++p) {
                float kv = kp[(size_t)p * W];
                acc[p] += st[(r0 + p + kh) * 36 + tx + kw] * kv;
            }
        }

#pragma unroll
    for (int p = 0; p < 4; ++p)
        out[((size_t)n * H + gy0 + r0 + p) * W + x] = acc[p];
}

// ---------------------------------------------------------------------------
// Launch sequence
// ---------------------------------------------------------------------------
extern "C" void kernel_launch(void* const* d_in, const int* in_sizes, int n_in,
                              void* d_out, int out_size)
{
    const float* x   = (const float*)d_in[0];
    const float* we1 = (const float*)d_in[1];
    const float* we2 = (const float*)d_in[2];
    const float* we3 = (const float*)d_in[3];
    const float* wd1 = (const float*)d_in[4];
    const float* wd2 = (const float*)d_in[5];
    const float* wk1 = (const float*)d_in[6];
    const float* wk2 = (const float*)d_in[7];
    const float* wk3 = (const float*)d_in[8];
    const float* wk4 = (const float*)d_in[9];
    float* out = (float*)d_out;

    float *bufA, *bufB, *hbuf;
    cudaGetSymbolAddress((void**)&bufA, g_bufA);
    cudaGetSymbolAddress((void**)&bufB, g_bufB);
    cudaGetSymbolAddress((void**)&hbuf, g_h);

    // dynamic smem sizes for the tf32 conv instantiations
    constexpr int ICH = 10 * 36;
    const int smem_k2 = (32 * ICH + 9 * 4 * 8 * 32 * 2) * 4;   // 119808 B
    const int smem_k3 = (64 * ICH + 9 * 8 * 4 * 32 * 2) * 4;   // 165888 B
    const int smem_k4 = (32 * ICH + 9 * 4 * 4 * 32 * 2) * 4;   //  82944 B

    cudaFuncSetAttribute(conv3x3_tf32_k<32, 64, 64>,
                         cudaFuncAttributeMaxDynamicSharedMemorySize, smem_k2);
    cudaFuncSetAttribute(conv3x3_tf32_k<64, 32, 32>,
                         cudaFuncAttributeMaxDynamicSharedMemorySize, smem_k3);
    cudaFuncSetAttribute(conv3x3_tf32_k<32, 32, 25>,
                         cudaFuncAttributeMaxDynamicSharedMemorySize, smem_k4);

    const dim3 blk(256);

    // encoder / decoder @ 256x256 (N=2), fp32
    conv3x3_relu_k<1, 16, 4><<<dim3(8, 8, 2), blk>>>(x,    we1, bufA, 256, 256, 16);
    conv3x3_relu_k<16, 16, 4><<<dim3(8, 8, 4), blk>>>(bufA, we2, bufB, 256, 256, 32);
    conv3x3_relu_k<32, 16, 4><<<dim3(8, 8, 8), blk>>>(bufB, we3, bufA, 256, 256, 64);
    conv3x3_relu_k<64, 16, 4><<<dim3(8, 8, 4), blk>>>(bufA, wd1, bufB, 256, 256, 32);
    conv3x3_relu_k<32, 16, 4><<<dim3(8, 8, 2), blk>>>(bufB, wd2, bufA, 256, 256, 16);

    // pixel shuffle + relu -> (2,1,1024,1024)
    shuffle_relu_k<<<8192, 256>>>(bufA, hbuf);

    // kernel-prediction branch @ 1024x1024
    conv3x3_relu_k<1, 16, 4><<<dim3(32, 32, 4), blk>>>(hbuf, wk1, bufB, 1024, 1024, 32);

    const dim3 g1024(32, 128, 2);
    conv3x3_tf32_k<32, 64, 64><<<g1024, blk, smem_k2>>>(bufB, wk2, bufA);
    conv3x3_tf32_k<64, 32, 32><<<g1024, blk, smem_k3>>>(bufA, wk3, bufB);
    conv3x3_tf32_k<32, 32, 25><<<g1024, blk, smem_k4>>>(bufB, wk4, bufA);

    // per-pixel 5x5 conv + residual add
    pixel_conv_add_k<<<dim3(32, 32, 2), blk>>>(hbuf, bufA, out);
}

// round 4
// speedup vs baseline: 4.1106x; 1.5859x over previous
#include <cuda_runtime.h>
#include <cuda_bf16.h>
#include <cstddef>

// ---------------------------------------------------------------------------
// Scratch buffers (no cudaMalloc allowed).
// ---------------------------------------------------------------------------
__device__ float g_bufA[134217728];   // 512 MB
__device__ float g_bufB[67108864];    // 256 MB
__device__ float g_h[2097152];        // 8 MB : shuffled image

// ---------------------------------------------------------------------------
// TF32 helpers
// ---------------------------------------------------------------------------
__device__ __forceinline__ unsigned f2tf32(float f) {
    unsigned r;
    asm("cvt.rna.tf32.f32 %0, %1;" : "=r"(r) : "f"(f));
    return r;
}

__device__ __forceinline__ void mma_tf32(float* c,
                                         unsigned a0, unsigned a1, unsigned a2, unsigned a3,
                                         unsigned b0, unsigned b1) {
    asm volatile("mma.sync.aligned.m16n8k8.row.col.f32.tf32.tf32.f32 "
                 "{%0,%1,%2,%3}, {%4,%5,%6,%7}, {%8,%9}, {%0,%1,%2,%3};"
                 : "+f"(c[0]), "+f"(c[1]), "+f"(c[2]), "+f"(c[3])
                 : "r"(a0), "r"(a1), "r"(a2), "r"(a3), "r"(b0), "r"(b1));
}

__device__ __forceinline__ void cp_async4(unsigned dst, const float* src, bool ok) {
    int sz = ok ? 4 : 0;
    asm volatile("cp.async.ca.shared.global [%0], [%1], 4, %2;"
                 :: "r"(dst), "l"(src), "r"(sz));
}

// ---------------------------------------------------------------------------
// TF32 3x3 SAME conv + ReLU, NCHW / OIHW, chunked over CI with cp.async
// double buffering.
//   Block: 256 threads (8 warps). Pixel tile 32(x) x 8(y); warp w owns row w.
//   Each warp: 2 M-tiles x NT N-tiles, K via 9 taps x (16/8) k-steps per chunk.
//   Chunk ci in groups of 16; input chunk + weight fragments double-buffered.
//   COR = real CO (<= NT*8, store-masked).
// ---------------------------------------------------------------------------
template <int CI, int NT, int COR, int H, int W, int MINB>
__global__ __launch_bounds__(256, MINB)
void conv3x3_tf32_v2(const float* __restrict__ in, const float* __restrict__ w,
                     float* __restrict__ out)
{
    constexpr int CC  = (CI < 16) ? CI : 16;   // channels per chunk
    constexpr int NCH = CI / CC;               // chunks
    constexpr int KSC = CC / 8;                // k-steps per chunk
    constexpr int IPITCH = 36;
    constexpr int ICH = 10 * IPITCH;           // 360 floats per channel slice
    constexpr int ISZ = CC * ICH;              // floats per input buffer
    constexpr int WCNT = 9 * KSC * NT * 32;    // uint2 fragments per buffer
    constexpr int EMAX = (WCNT + 255) / 256;

    extern __shared__ float smem_f[];
    float* in_s = smem_f;                        // [2][ISZ] raw fp32
    uint2* ws   = (uint2*)(smem_f + 2 * ISZ);    // [2][WCNT] tf32 frags

    const int tid  = threadIdx.x;
    const int lane = tid & 31;
    const int wrp  = tid >> 5;
    const int gx0  = blockIdx.x * 32;
    const int gy0  = blockIdx.y * 8;
    const int img  = blockIdx.z;

    const float* inN = in + (size_t)img * CI * H * W;

    // ---- input chunk fill via cp.async (raw fp32) ----
    auto fill = [&](int ch, int buf) {
        const float* base = inN + (size_t)ch * CC * H * W;
        for (int i = tid; i < CC * 340; i += 256) {
            int ci = i / 340, rem = i % 340;
            int r = rem / 34, c = rem % 34;
            int gy = gy0 + r - 1, gx = gx0 + c - 1;
            bool ok = ((unsigned)gy < (unsigned)H) && ((unsigned)gx < (unsigned)W);
            const float* src = ok ? base + (size_t)ci * H * W + gy * W + gx : base;
            unsigned dst = (unsigned)__cvta_generic_to_shared(
                in_s + buf * ISZ + ci * ICH + r * IPITCH + c);
            cp_async4(dst, src, ok);
        }
        asm volatile("cp.async.commit_group;");
    };

    // ---- weight fragment gather (gmem -> regs), and regs -> smem ----
    float2 wr[EMAX];
    auto ldgw = [&](int ch) {
#pragma unroll
        for (int j = 0; j < EMAX; ++j) {
            int e = tid + j * 256;
            float b0 = 0.f, b1 = 0.f;
            if (e < WCNT) {
                int l = e & 31, r = e >> 5;
                int n = r % NT; r /= NT;
                int k = r % KSC; int t = r / KSC;
                int co = n * 8 + (l >> 2);
                int ci = ch * CC + k * 8 + (l & 3);
                if (co < COR) {
                    b0 = w[(co * CI + ci) * 9 + t];
                    b1 = w[(co * CI + ci + 4) * 9 + t];
                }
            }
            wr[j] = make_float2(b0, b1);
        }
    };
    auto stsw = [&](int buf) {
#pragma unroll
        for (int j = 0; j < EMAX; ++j) {
            int e = tid + j * 256;
            if (e < WCNT)
                ws[buf * WCNT + e] = make_uint2(f2tf32(wr[j].x), f2tf32(wr[j].y));
        }
    };

    float acc[2][NT][4];
#pragma unroll
    for (int m = 0; m < 2; ++m)
#pragma unroll
        for (int n = 0; n < NT; ++n)
#pragma unroll
            for (int i = 0; i < 4; ++i) acc[m][n][i] = 0.f;

    // prologue: chunk 0
    fill(0, 0);
    ldgw(0);
    stsw(0);
    asm volatile("cp.async.wait_group 0;");
    __syncthreads();

    const int arow = lane >> 2;
    const int aci  = lane & 3;

    for (int ch = 0; ch < NCH; ++ch) {
        const int buf = ch & 1;
        if (ch + 1 < NCH) {
            fill(ch + 1, buf ^ 1);   // overlaps compute below
            ldgw(ch + 1);            // L2-latency hidden by compute
        }

        const float* A = in_s + buf * ISZ;
        const uint2* B = ws + buf * WCNT;
#pragma unroll
        for (int kh = 0; kh < 3; ++kh) {
#pragma unroll
            for (int kw = 0; kw < 3; ++kw) {
                const int t = kh * 3 + kw;
                const int roff = (wrp + kh) * IPITCH + kw + arow;
#pragma unroll
                for (int k = 0; k < KSC; ++k) {
                    const int ab = (k * 8 + aci) * ICH + roff;
                    unsigned a00 = f2tf32(A[ab]);
                    unsigned a01 = f2tf32(A[ab + 8]);
                    unsigned a02 = f2tf32(A[ab + 4 * ICH]);
                    unsigned a03 = f2tf32(A[ab + 4 * ICH + 8]);
                    unsigned a10 = f2tf32(A[ab + 16]);
                    unsigned a11 = f2tf32(A[ab + 24]);
                    unsigned a12 = f2tf32(A[ab + 4 * ICH + 16]);
                    unsigned a13 = f2tf32(A[ab + 4 * ICH + 24]);
                    const uint2* wb = B + (t * KSC + k) * NT * 32 + lane;
#pragma unroll
                    for (int n = 0; n < NT; ++n) {
                        uint2 b = wb[n * 32];
                        mma_tf32(acc[0][n], a00, a01, a02, a03, b.x, b.y);
                        mma_tf32(acc[1][n], a10, a11, a12, a13, b.x, b.y);
                    }
                }
            }
        }

        if (ch + 1 < NCH) {
            stsw(buf ^ 1);
            asm volatile("cp.async.wait_group 0;");
            __syncthreads();
        }
    }

    // ---- epilogue: ReLU + store ----
    const int y = gy0 + wrp;
#pragma unroll
    for (int m = 0; m < 2; ++m) {
        const int x0 = gx0 + m * 16 + arow;
#pragma unroll
        for (int n = 0; n < NT; ++n) {
            const int coA = n * 8 + 2 * (lane & 3);
            float v0 = fmaxf(acc[m][n][0], 0.f);
            float v1 = fmaxf(acc[m][n][1], 0.f);
            float v2 = fmaxf(acc[m][n][2], 0.f);
            float v3 = fmaxf(acc[m][n][3], 0.f);
            if (coA < COR) {
                float* p = out + ((size_t)(img * COR + coA) * H + y) * W;
                p[x0]     = v0;
                p[x0 + 8] = v2;
            }
            if (coA + 1 < COR) {
                float* p = out + ((size_t)(img * COR + coA + 1) * H + y) * W;
                p[x0]     = v1;
                p[x0 + 8] = v3;
            }
        }
    }
}

// ---------------------------------------------------------------------------
// fp32 3x3 conv + ReLU (only for CI=1 layers: e1, k1).
// ---------------------------------------------------------------------------
template <int CI, int COT, int PX>
__global__ __launch_bounds__(256)
void conv3x3_relu_k(const float* __restrict__ in, const float* __restrict__ w,
                    float* __restrict__ out, int H, int W, int CO)
{
    constexpr int TW = 32;
    constexpr int TH = 8 * PX;
    __shared__ float st[(TH + 2) * (TW + 2)];
    __shared__ float ws[COT * CI * 9];

    const int tid = threadIdx.x;
    const int tx = tid & 31;
    const int ty = tid >> 5;

    const int groups = CO / COT;
    const int g  = blockIdx.z % groups;
    const int n  = blockIdx.z / groups;
    const int co0 = g * COT;

    for (int i = tid; i < COT * CI * 9; i += 256)
        ws[i] = w[co0 * CI * 9 + i];

    const int gx0 = blockIdx.x * TW;
    const int gy0 = blockIdx.y * TH;

    float acc[PX][COT];
#pragma unroll
    for (int p = 0; p < PX; ++p)
#pragma unroll
        for (int c = 0; c < COT; ++c) acc[p][c] = 0.f;

    const float* inN = in + (size_t)n * CI * H * W;
    const int r0 = ty * PX;

    for (int ci = 0; ci < CI; ++ci) {
        __syncthreads();
        const float* ip = inN + (size_t)ci * H * W;
        for (int i = tid; i < (TH + 2) * (TW + 2); i += 256) {
            int r = i / (TW + 2), c = i % (TW + 2);
            int gy = gy0 + r - 1, gx = gx0 + c - 1;
            st[i] = (gy >= 0 && gy < H && gx >= 0 && gx < W) ? ip[gy * W + gx] : 0.f;
        }
        __syncthreads();

        float v[PX + 2][3];
#pragma unroll
        for (int dy = 0; dy < PX + 2; ++dy)
#pragma unroll
            for (int dx = 0; dx < 3; ++dx)
                v[dy][dx] = st[(r0 + dy) * (TW + 2) + tx + dx];

        const float* wci = ws + ci * 9;
#pragma unroll
        for (int c = 0; c < COT; ++c) {
            const float* wp = wci + c * CI * 9;
#pragma unroll
            for (int kh = 0; kh < 3; ++kh)
#pragma unroll
                for (int kw = 0; kw < 3; ++kw) {
                    float wv = wp[kh * 3 + kw];
#pragma unroll
                    for (int p = 0; p < PX; ++p)
                        acc[p][c] += v[p + kh][kw] * wv;
                }
        }
    }

#pragma unroll
    for (int c = 0; c < COT; ++c) {
        float* op = out + ((size_t)(n * CO + co0 + c) * H + gy0 + r0) * W + gx0 + tx;
#pragma unroll
        for (int p = 0; p < PX; ++p) {
            float vv = acc[p][c];
            op[(size_t)p * W] = vv > 0.f ? vv : 0.f;
        }
    }
}

// ---------------------------------------------------------------------------
// PixelShuffle(4) + ReLU: (2,16,256,256) -> (2,1,1024,1024)
// ---------------------------------------------------------------------------
__global__ void shuffle_relu_k(const float* __restrict__ in, float* __restrict__ out)
{
    int idx = blockIdx.x * blockDim.x + threadIdx.x;
    int x = idx & 1023;
    int y = (idx >> 10) & 1023;
    int n = idx >> 20;
    int c = ((y & 3) << 2) | (x & 3);
    int hh = y >> 2, ww = x >> 2;
    float v = in[(((size_t)(n * 16 + c) * 256) + hh) * 256 + ww];
    out[idx] = v > 0.f ? v : 0.f;
}

// ---------------------------------------------------------------------------
// Per-pixel 5x5 dynamic conv + residual add.
// ---------------------------------------------------------------------------
__global__ __launch_bounds__(256)
void pixel_conv_add_k(const float* __restrict__ h, const float* __restrict__ ker,
                      float* __restrict__ out)
{
    constexpr int H = 1024, W = 1024;
    __shared__ float st[36 * 36];
    const int tid = threadIdx.x;
    const int tx = tid & 31, ty = tid >> 5;
    const int n = blockIdx.z;
    const int gx0 = blockIdx.x * 32, gy0 = blockIdx.y * 32;

    const float* hp = h + (size_t)n * H * W;
    for (int i = tid; i < 36 * 36; i += 256) {
        int r = i / 36, c = i % 36;
        int gy = gy0 + r - 2, gx = gx0 + c - 2;
        st[i] = (gy >= 0 && gy < H && gx >= 0 && gx < W) ? hp[gy * W + gx] : 0.f;
    }
    __syncthreads();

    const int r0 = ty * 4;
    const int x = gx0 + tx;
    float acc[4];
#pragma unroll
    for (int p = 0; p < 4; ++p)
        acc[p] = st[(r0 + p + 2) * 36 + tx + 2];  // residual h

#pragma unroll
    for (int kw = 0; kw < 5; ++kw)
#pragma unroll
        for (int kh = 0; kh < 5; ++kh) {
            const int j = kw * 5 + kh;
            const float* kp = ker + ((size_t)(n * 25 + j) * H + gy0 + r0) * W + x;
#pragma unroll
            for (int p = 0; p < 4; ++p) {
                float kv = kp[(size_t)p * W];
                acc[p] += st[(r0 + p + kh) * 36 + tx + kw] * kv;
            }
        }

#pragma unroll
    for (int p = 0; p < 4; ++p)
        out[((size_t)n * H + gy0 + r0 + p) * W + x] = acc[p];
}

// ---------------------------------------------------------------------------
// Launch sequence
// ---------------------------------------------------------------------------
extern "C" void kernel_launch(void* const* d_in, const int* in_sizes, int n_in,
                              void* d_out, int out_size)
{
    const float* x   = (const float*)d_in[0];
    const float* we1 = (const float*)d_in[1];
    const float* we2 = (const float*)d_in[2];
    const float* we3 = (const float*)d_in[3];
    const float* wd1 = (const float*)d_in[4];
    const float* wd2 = (const float*)d_in[5];
    const float* wk1 = (const float*)d_in[6];
    const float* wk2 = (const float*)d_in[7];
    const float* wk3 = (const float*)d_in[8];
    const float* wk4 = (const float*)d_in[9];
    float* out = (float*)d_out;

    float *bufA, *bufB, *hbuf;
    cudaGetSymbolAddress((void**)&bufA, g_bufA);
    cudaGetSymbolAddress((void**)&bufB, g_bufB);
    cudaGetSymbolAddress((void**)&hbuf, g_h);

    // dynamic smem: 2*CC*360*4 (input) + 2*9*(CC/8)*NT*32*8 (weights)
    auto smem_of = [](int CC, int NT) {
        return 2 * CC * 360 * 4 + 2 * 9 * (CC / 8) * NT * 32 * 8;
    };
    const int sm_nt2 = smem_of(16, 2);   //  64512
    const int sm_nt4 = smem_of(16, 4);   //  82944
    const int sm_nt8 = smem_of(16, 8);   // 119808

    // instantiations:                     CI  NT COR   H    W   MINB
    cudaFuncSetAttribute(conv3x3_tf32_v2<16, 4, 32, 256, 256, 2>,
                         cudaFuncAttributeMaxDynamicSharedMemorySize, sm_nt4);
    cudaFuncSetAttribute(conv3x3_tf32_v2<32, 8, 64, 256, 256, 1>,
                         cudaFuncAttributeMaxDynamicSharedMemorySize, sm_nt8);
    cudaFuncSetAttribute(conv3x3_tf32_v2<64, 4, 32, 256, 256, 2>,
                         cudaFuncAttributeMaxDynamicSharedMemorySize, sm_nt4);
    cudaFuncSetAttribute(conv3x3_tf32_v2<32, 2, 16, 256, 256, 2>,
                         cudaFuncAttributeMaxDynamicSharedMemorySize, sm_nt2);
    cudaFuncSetAttribute(conv3x3_tf32_v2<32, 8, 64, 1024, 1024, 1>,
                         cudaFuncAttributeMaxDynamicSharedMemorySize, sm_nt8);
    cudaFuncSetAttribute(conv3x3_tf32_v2<64, 4, 32, 1024, 1024, 2>,
                         cudaFuncAttributeMaxDynamicSharedMemorySize, sm_nt4);
    cudaFuncSetAttribute(conv3x3_tf32_v2<32, 4, 25, 1024, 1024, 2>,
                         cudaFuncAttributeMaxDynamicSharedMemorySize, sm_nt4);

    const dim3 blk(256);
    const dim3 g256(8, 32, 2);
    const dim3 g1024(32, 128, 2);

    // encoder / decoder @ 256x256 (N=2)
    conv3x3_relu_k<1, 16, 4><<<dim3(8, 8, 2), blk>>>(x, we1, bufA, 256, 256, 16);
    conv3x3_tf32_v2<16, 4, 32, 256, 256, 2><<<g256, blk, sm_nt4>>>(bufA, we2, bufB);
    conv3x3_tf32_v2<32, 8, 64, 256, 256, 1><<<g256, blk, sm_nt8>>>(bufB, we3, bufA);
    conv3x3_tf32_v2<64, 4, 32, 256, 256, 2><<<g256, blk, sm_nt4>>>(bufA, wd1, bufB);
    conv3x3_tf32_v2<32, 2, 16, 256, 256, 2><<<g256, blk, sm_nt2>>>(bufB, wd2, bufA);

    // pixel shuffle + relu -> (2,1,1024,1024)
    shuffle_relu_k<<<8192, 256>>>(bufA, hbuf);

    // kernel-prediction branch @ 1024x1024
    conv3x3_relu_k<1, 16, 4><<<dim3(32, 32, 4), blk>>>(hbuf, wk1, bufB, 1024, 1024, 32);
    conv3x3_tf32_v2<32, 8, 64, 1024, 1024, 1><<<g1024, blk, sm_nt8>>>(bufB, wk2, bufA);
    conv3x3_tf32_v2<64, 4, 32, 1024, 1024, 2><<<g1024, blk, sm_nt4>>>(bufA, wk3, bufB);
    conv3x3_tf32_v2<32, 4, 25, 1024, 1024, 2><<<g1024, blk, sm_nt4>>>(bufB, wk4, bufA);

    // per-pixel 5x5 conv + residual add
    pixel_conv_add_k<<<dim3(32, 32, 2), blk>>>(hbuf, bufA, out);
}

// round 5
// speedup vs baseline: 4.1516x; 1.0100x over previous
#include <cuda_runtime.h>
#include <cuda_bf16.h>
#include <cstddef>

// ---------------------------------------------------------------------------
// Scratch buffers (no cudaMalloc allowed).
// ---------------------------------------------------------------------------
__device__ float g_bufA[134217728];   // 512 MB
__device__ float g_bufB[67108864];    // 256 MB
__device__ float g_h[2097152];        // 8 MB : shuffled image

// ---------------------------------------------------------------------------
// TF32 helpers
// ---------------------------------------------------------------------------
__device__ __forceinline__ unsigned f2tf32(float f) {
    unsigned r;
    asm("cvt.rna.tf32.f32 %0, %1;" : "=r"(r) : "f"(f));
    return r;
}

__device__ __forceinline__ float round_tf32(float f) {
    unsigned r;
    asm("cvt.rna.tf32.f32 %0, %1;" : "=r"(r) : "f"(f));
    return __uint_as_float(r);
}

__device__ __forceinline__ void mma_tf32(float* c,
                                         unsigned a0, unsigned a1, unsigned a2, unsigned a3,
                                         unsigned b0, unsigned b1) {
    asm volatile("mma.sync.aligned.m16n8k8.row.col.f32.tf32.tf32.f32 "
                 "{%0,%1,%2,%3}, {%4,%5,%6,%7}, {%8,%9}, {%0,%1,%2,%3};"
                 : "+f"(c[0]), "+f"(c[1]), "+f"(c[2]), "+f"(c[3])
                 : "r"(a0), "r"(a1), "r"(a2), "r"(a3), "r"(b0), "r"(b1));
}

__device__ __forceinline__ void cp_async4(unsigned dst, const float* src, bool ok) {
    int sz = ok ? 4 : 0;
    asm volatile("cp.async.ca.shared.global [%0], [%1], 4, %2;"
                 :: "r"(dst), "l"(src), "r"(sz));
}

// ---------------------------------------------------------------------------
// TF32 3x3 SAME conv + ReLU, NCHW / OIHW.
//   Inputs MUST already be tf32-valued fp32 (producers round at epilogue).
//   Block: 256 threads (8 warps), pixel tile 32x8, warp w owns row w.
//   Warp computes 2 M-tiles (16px) x NT N-tiles (8 co).
//   CI chunked by 16 with cp.async double buffering of input + weights.
//   CO is split into groups of NT*8 channels via blockIdx.z.
//   ROUND: round outputs to tf32 (when the consumer is another tf32 conv).
// ---------------------------------------------------------------------------
template <int CI, int NT, int COT, int H, int W, int MINB, bool ROUND>
__global__ __launch_bounds__(256, MINB)
void conv3x3_tf32_v3(const float* __restrict__ in, const float* __restrict__ w,
                     float* __restrict__ out)
{
    constexpr int CC  = 16;                 // channels per chunk
    constexpr int NCH = CI / CC;            // chunks
    constexpr int KSC = CC / 8;             // k-steps per chunk (2)
    constexpr int IPITCH = 36;
    constexpr int ICH = 10 * IPITCH;        // 360
    constexpr int ISZ = CC * ICH;           // 5760 words per input buffer
    constexpr int NPAIR = NT / 2;
    constexpr int WCNT = 9 * KSC * NPAIR * 32;   // uint4 fragments per buffer
    constexpr int EMAX = (WCNT + 255) / 256;
    constexpr int GROUPS = (COT + NT * 8 - 1) / (NT * 8);

    extern __shared__ unsigned smem_u[];
    unsigned* in_s = smem_u;                       // [2][ISZ] tf32 bits
    uint4*    ws   = (uint4*)(smem_u + 2 * ISZ);   // [2][WCNT]

    const int tid  = threadIdx.x;
    const int lane = tid & 31;
    const int wrp  = tid >> 5;
    const int gx0  = blockIdx.x * 32;
    const int gy0  = blockIdx.y * 8;
    const int img  = blockIdx.z / GROUPS;
    const int co0  = (blockIdx.z % GROUPS) * NT * 8;

    const float* inN = in + (size_t)img * CI * H * W;

    // ---- input chunk fill via cp.async (raw bits, already tf32-valued) ----
    auto fill = [&](int ch, int buf) {
        const float* base = inN + (size_t)ch * CC * H * W;
        for (int i = tid; i < CC * 340; i += 256) {
            int ci = i / 340, rem = i % 340;
            int r = rem / 34, c = rem % 34;
            int gy = gy0 + r - 1, gx = gx0 + c - 1;
            bool ok = ((unsigned)gy < (unsigned)H) && ((unsigned)gx < (unsigned)W);
            const float* src = ok ? base + (size_t)ci * H * W + gy * W + gx : base;
            unsigned dst = (unsigned)__cvta_generic_to_shared(
                in_s + buf * ISZ + ci * ICH + r * IPITCH + c);
            cp_async4(dst, src, ok);
        }
        asm volatile("cp.async.commit_group;");
    };

    // ---- weight fragments: gmem -> regs -> smem (tf32, uint4 = 2 n-tiles) ----
    float4 wr[EMAX];
    auto ldgw = [&](int ch) {
#pragma unroll
        for (int j = 0; j < EMAX; ++j) {
            int e = tid + j * 256;
            float b0 = 0.f, b1 = 0.f, b2 = 0.f, b3 = 0.f;
            if (e < WCNT) {
                int l = e & 31, r = e >> 5;
                int p = r % NPAIR; r /= NPAIR;
                int k = r % KSC; int t = r / KSC;
                int coa = co0 + (2 * p) * 8 + (l >> 2);
                int cob = coa + 8;
                int ci = ch * CC + k * 8 + (l & 3);
                if (coa < COT) {
                    b0 = w[(coa * CI + ci) * 9 + t];
                    b1 = w[(coa * CI + ci + 4) * 9 + t];
                }
                if (cob < COT) {
                    b2 = w[(cob * CI + ci) * 9 + t];
                    b3 = w[(cob * CI + ci + 4) * 9 + t];
                }
            }
            wr[j] = make_float4(b0, b1, b2, b3);
        }
    };
    auto stsw = [&](int buf) {
#pragma unroll
        for (int j = 0; j < EMAX; ++j) {
            int e = tid + j * 256;
            if (e < WCNT)
                ws[buf * WCNT + e] = make_uint4(f2tf32(wr[j].x), f2tf32(wr[j].y),
                                                f2tf32(wr[j].z), f2tf32(wr[j].w));
        }
    };

    float acc[2][NT][4];
#pragma unroll
    for (int m = 0; m < 2; ++m)
#pragma unroll
        for (int n = 0; n < NT; ++n)
#pragma unroll
            for (int i = 0; i < 4; ++i) acc[m][n][i] = 0.f;

    fill(0, 0);
    ldgw(0);
    stsw(0);
    asm volatile("cp.async.wait_group 0;");
    __syncthreads();

    const int arow = lane >> 2;
    const int aci  = lane & 3;

    for (int ch = 0; ch < NCH; ++ch) {
        const int buf = ch & 1;
        if (ch + 1 < NCH) {
            fill(ch + 1, buf ^ 1);
            ldgw(ch + 1);
        }

        const unsigned* A = in_s + buf * ISZ;
        const uint4*    B = ws + buf * WCNT;
#pragma unroll
        for (int kh = 0; kh < 3; ++kh) {
#pragma unroll
            for (int kw = 0; kw < 3; ++kw) {
                const int t = kh * 3 + kw;
                const int roff = (wrp + kh) * IPITCH + kw + arow;
#pragma unroll
                for (int k = 0; k < KSC; ++k) {
                    const int ab = (k * 8 + aci) * ICH + roff;
                    unsigned a00 = A[ab];
                    unsigned a01 = A[ab + 8];
                    unsigned a02 = A[ab + 4 * ICH];
                    unsigned a03 = A[ab + 4 * ICH + 8];
                    unsigned a10 = A[ab + 16];
                    unsigned a11 = A[ab + 24];
                    unsigned a12 = A[ab + 4 * ICH + 16];
                    unsigned a13 = A[ab + 4 * ICH + 24];
                    const uint4* wb = B + (t * KSC + k) * NPAIR * 32 + lane;
#pragma unroll
                    for (int p = 0; p < NPAIR; ++p) {
                        uint4 b = wb[p * 32];
                        mma_tf32(acc[0][2 * p],     a00, a01, a02, a03, b.x, b.y);
                        mma_tf32(acc[1][2 * p],     a10, a11, a12, a13, b.x, b.y);
                        mma_tf32(acc[0][2 * p + 1], a00, a01, a02, a03, b.z, b.w);
                        mma_tf32(acc[1][2 * p + 1], a10, a11, a12, a13, b.z, b.w);
                    }
                }
            }
        }

        if (ch + 1 < NCH) {
            stsw(buf ^ 1);
            asm volatile("cp.async.wait_group 0;");
            __syncthreads();
        }
    }

    // ---- epilogue: ReLU (+ optional tf32 rounding) + store ----
    const int y = gy0 + wrp;
#pragma unroll
    for (int m = 0; m < 2; ++m) {
        const int x0 = gx0 + m * 16 + arow;
#pragma unroll
        for (int n = 0; n < NT; ++n) {
            const int coA = co0 + n * 8 + 2 * (lane & 3);
            float v0 = fmaxf(acc[m][n][0], 0.f);
            float v1 = fmaxf(acc[m][n][1], 0.f);
            float v2 = fmaxf(acc[m][n][2], 0.f);
            float v3 = fmaxf(acc[m][n][3], 0.f);
            if (ROUND) {
                v0 = round_tf32(v0); v1 = round_tf32(v1);
                v2 = round_tf32(v2); v3 = round_tf32(v3);
            }
            if (coA < COT) {
                float* p = out + ((size_t)(img * COT + coA) * H + y) * W;
                p[x0]     = v0;
                p[x0 + 8] = v2;
            }
            if (coA + 1 < COT) {
                float* p = out + ((size_t)(img * COT + coA + 1) * H + y) * W;
                p[x0]     = v1;
                p[x0 + 8] = v3;
            }
        }
    }
}

// ---------------------------------------------------------------------------
// fp32 3x3 conv + ReLU (CI=1 layers: e1, k1). Optionally round outputs tf32.
// ---------------------------------------------------------------------------
template <int CI, int COT, int PX, bool ROUND>
__global__ __launch_bounds__(256)
void conv3x3_relu_k(const float* __restrict__ in, const float* __restrict__ w,
                    float* __restrict__ out, int H, int W, int CO)
{
    constexpr int TW = 32;
    constexpr int TH = 8 * PX;
    __shared__ float st[(TH + 2) * (TW + 2)];
    __shared__ float ws[COT * CI * 9];

    const int tid = threadIdx.x;
    const int tx = tid & 31;
    const int ty = tid >> 5;

    const int groups = CO / COT;
    const int g  = blockIdx.z % groups;
    const int n  = blockIdx.z / groups;
    const int co0 = g * COT;

    for (int i = tid; i < COT * CI * 9; i += 256)
        ws[i] = w[co0 * CI * 9 + i];

    const int gx0 = blockIdx.x * TW;
    const int gy0 = blockIdx.y * TH;

    float acc[PX][COT];
#pragma unroll
    for (int p = 0; p < PX; ++p)
#pragma unroll
        for (int c = 0; c < COT; ++c) acc[p][c] = 0.f;

    const float* inN = in + (size_t)n * CI * H * W;
    const int r0 = ty * PX;

    for (int ci = 0; ci < CI; ++ci) {
        __syncthreads();
        const float* ip = inN + (size_t)ci * H * W;
        for (int i = tid; i < (TH + 2) * (TW + 2); i += 256) {
            int r = i / (TW + 2), c = i % (TW + 2);
            int gy = gy0 + r - 1, gx = gx0 + c - 1;
            st[i] = (gy >= 0 && gy < H && gx >= 0 && gx < W) ? ip[gy * W + gx] : 0.f;
        }
        __syncthreads();

        float v[PX + 2][3];
#pragma unroll
        for (int dy = 0; dy < PX + 2; ++dy)
#pragma unroll
            for (int dx = 0; dx < 3; ++dx)
                v[dy][dx] = st[(r0 + dy) * (TW + 2) + tx + dx];

        const float* wci = ws + ci * 9;
#pragma unroll
        for (int c = 0; c < COT; ++c) {
            const float* wp = wci + c * CI * 9;
#pragma unroll
            for (int kh = 0; kh < 3; ++kh)
#pragma unroll
                for (int kw = 0; kw < 3; ++kw) {
                    float wv = wp[kh * 3 + kw];
#pragma unroll
                    for (int p = 0; p < PX; ++p)
                        acc[p][c] += v[p + kh][kw] * wv;
                }
        }
    }

#pragma unroll
    for (int c = 0; c < COT; ++c) {
        float* op = out + ((size_t)(n * CO + co0 + c) * H + gy0 + r0) * W + gx0 + tx;
#pragma unroll
        for (int p = 0; p < PX; ++p) {
            float vv = fmaxf(acc[p][c], 0.f);
            if (ROUND) vv = round_tf32(vv);
            op[(size_t)p * W] = vv;
        }
    }
}

// ---------------------------------------------------------------------------
// PixelShuffle(4) + ReLU: (2,16,256,256) -> (2,1,1024,1024)
// ---------------------------------------------------------------------------
__global__ void shuffle_relu_k(const float* __restrict__ in, float* __restrict__ out)
{
    int idx = blockIdx.x * blockDim.x + threadIdx.x;
    int x = idx & 1023;
    int y = (idx >> 10) & 1023;
    int n = idx >> 20;
    int c = ((y & 3) << 2) | (x & 3);
    int hh = y >> 2, ww = x >> 2;
    float v = in[(((size_t)(n * 16 + c) * 256) + hh) * 256 + ww];
    out[idx] = v > 0.f ? v : 0.f;
}

// ---------------------------------------------------------------------------
// Per-pixel 5x5 dynamic conv + residual add.
// ---------------------------------------------------------------------------
__global__ __launch_bounds__(256)
void pixel_conv_add_k(const float* __restrict__ h, const float* __restrict__ ker,
                      float* __restrict__ out)
{
    constexpr int H = 1024, W = 1024;
    __shared__ float st[36 * 36];
    const int tid = threadIdx.x;
    const int tx = tid & 31, ty = tid >> 5;
    const int n = blockIdx.z;
    const int gx0 = blockIdx.x * 32, gy0 = blockIdx.y * 32;

    const float* hp = h + (size_t)n * H * W;
    for (int i = tid; i < 36 * 36; i += 256) {
        int r = i / 36, c = i % 36;
        int gy = gy0 + r - 2, gx = gx0 + c - 2;
        st[i] = (gy >= 0 && gy < H && gx >= 0 && gx < W) ? hp[gy * W + gx] : 0.f;
    }
    __syncthreads();

    const int r0 = ty * 4;
    const int x = gx0 + tx;
    float acc[4];
#pragma unroll
    for (int p = 0; p < 4; ++p)
        acc[p] = st[(r0 + p + 2) * 36 + tx + 2];  // residual h

#pragma unroll
    for (int kw = 0; kw < 5; ++kw)
#pragma unroll
        for (int kh = 0; kh < 5; ++kh) {
            const int j = kw * 5 + kh;
            const float* kp = ker + ((size_t)(n * 25 + j) * H + gy0 + r0) * W + x;
#pragma unroll
            for (int p = 0; p < 4; ++p) {
                float kv = kp[(size_t)p * W];
                acc[p] += st[(r0 + p + kh) * 36 + tx + kw] * kv;
            }
        }

#pragma unroll
    for (int p = 0; p < 4; ++p)
        out[((size_t)n * H + gy0 + r0 + p) * W + x] = acc[p];
}

// ---------------------------------------------------------------------------
// Launch sequence
// ---------------------------------------------------------------------------
extern "C" void kernel_launch(void* const* d_in, const int* in_sizes, int n_in,
                              void* d_out, int out_size)
{
    const float* x   = (const float*)d_in[0];
    const float* we1 = (const float*)d_in[1];
    const float* we2 = (const float*)d_in[2];
    const float* we3 = (const float*)d_in[3];
    const float* wd1 = (const float*)d_in[4];
    const float* wd2 = (const float*)d_in[5];
    const float* wk1 = (const float*)d_in[6];
    const float* wk2 = (const float*)d_in[7];
    const float* wk3 = (const float*)d_in[8];
    const float* wk4 = (const float*)d_in[9];
    float* out = (float*)d_out;

    float *bufA, *bufB, *hbuf;
    cudaGetSymbolAddress((void**)&bufA, g_bufA);
    cudaGetSymbolAddress((void**)&bufB, g_bufB);
    cudaGetSymbolAddress((void**)&hbuf, g_h);

    // smem: 2*5760*4 (input) + 2*9*2*(NT/2)*32*16 (weights)
    const int sm_nt4 = 2 * 5760 * 4 + 2 * 1152 * 16;   // 82944
    const int sm_nt2 = 2 * 5760 * 4 + 2 * 576 * 16;    // 64512

    //                                CI NT COT   H     W  MINB ROUND
    cudaFuncSetAttribute(conv3x3_tf32_v3<16, 4, 32, 256, 256, 2, true>,
                         cudaFuncAttributeMaxDynamicSharedMemorySize, sm_nt4);
    cudaFuncSetAttribute(conv3x3_tf32_v3<32, 4, 64, 256, 256, 2, true>,
                         cudaFuncAttributeMaxDynamicSharedMemorySize, sm_nt4);
    cudaFuncSetAttribute(conv3x3_tf32_v3<64, 4, 32, 256, 256, 2, true>,
                         cudaFuncAttributeMaxDynamicSharedMemorySize, sm_nt4);
    cudaFuncSetAttribute(conv3x3_tf32_v3<32, 2, 16, 256, 256, 2, false>,
                         cudaFuncAttributeMaxDynamicSharedMemorySize, sm_nt2);
    cudaFuncSetAttribute(conv3x3_tf32_v3<32, 4, 64, 1024, 1024, 2, true>,
                         cudaFuncAttributeMaxDynamicSharedMemorySize, sm_nt4);
    cudaFuncSetAttribute(conv3x3_tf32_v3<64, 4, 32, 1024, 1024, 2, true>,
                         cudaFuncAttributeMaxDynamicSharedMemorySize, sm_nt4);
    cudaFuncSetAttribute(conv3x3_tf32_v3<32, 4, 25, 1024, 1024, 2, false>,
                         cudaFuncAttributeMaxDynamicSharedMemorySize, sm_nt4);

    const dim3 blk(256);

    // encoder / decoder @ 256x256 (N=2). e1 rounds its tf32-consumed output.
    conv3x3_relu_k<1, 16, 4, true><<<dim3(8, 8, 2), blk>>>(x, we1, bufA, 256, 256, 16);
    conv3x3_tf32_v3<16, 4, 32, 256, 256, 2, true ><<<dim3(8, 32, 2), blk, sm_nt4>>>(bufA, we2, bufB);
    conv3x3_tf32_v3<32, 4, 64, 256, 256, 2, true ><<<dim3(8, 32, 4), blk, sm_nt4>>>(bufB, we3, bufA);
    conv3x3_tf32_v3<64, 4, 32, 256, 256, 2, true ><<<dim3(8, 32, 2), blk, sm_nt4>>>(bufA, wd1, bufB);
    conv3x3_tf32_v3<32, 2, 16, 256, 256, 2, false><<<dim3(8, 32, 2), blk, sm_nt2>>>(bufB, wd2, bufA);

    // pixel shuffle + relu -> (2,1,1024,1024), full fp32
    shuffle_relu_k<<<8192, 256>>>(bufA, hbuf);

    // kernel-prediction branch @ 1024x1024. k1 rounds its output (feeds k2).
    conv3x3_relu_k<1, 16, 4, true><<<dim3(32, 32, 4), blk>>>(hbuf, wk1, bufB, 1024, 1024, 32);
    conv3x3_tf32_v3<32, 4, 64, 1024, 1024, 2, true ><<<dim3(32, 128, 4), blk, sm_nt4>>>(bufB, wk2, bufA);
    conv3x3_tf32_v3<64, 4, 32, 1024, 1024, 2, true ><<<dim3(32, 128, 2), blk, sm_nt4>>>(bufA, wk3, bufB);
    conv3x3_tf32_v3<32, 4, 25, 1024, 1024, 2, false><<<dim3(32, 128, 2), blk, sm_nt4>>>(bufB, wk4, bufA);

    // per-pixel 5x5 conv + residual add (full fp32)
    pixel_conv_add_k<<<dim3(32, 32, 2), blk>>>(hbuf, bufA, out);
}

// round 6
// speedup vs baseline: 6.4892x; 1.5631x over previous
#include <cuda_runtime.h>
#include <cuda_bf16.h>
#include <cstddef>

// ---------------------------------------------------------------------------
// Scratch buffers (no cudaMalloc allowed).
// ---------------------------------------------------------------------------
__device__ float g_bufA[134217728];   // 512 MB
__device__ float g_bufB[67108864];    // 256 MB
__device__ float g_h[2097152];        // 8 MB : shuffled image
__device__ uint4 g_wpack[23040];      // prepacked tf32 weight fragments (360 KB)

// ---------------------------------------------------------------------------
// TF32 helpers
// ---------------------------------------------------------------------------
__device__ __forceinline__ unsigned f2tf32(float f) {
    unsigned r;
    asm("cvt.rna.tf32.f32 %0, %1;" : "=r"(r) : "f"(f));
    return r;
}

__device__ __forceinline__ float round_tf32(float f) {
    unsigned r;
    asm("cvt.rna.tf32.f32 %0, %1;" : "=r"(r) : "f"(f));
    return __uint_as_float(r);
}

__device__ __forceinline__ void mma_tf32(float* c,
                                         unsigned a0, unsigned a1, unsigned a2, unsigned a3,
                                         unsigned b0, unsigned b1) {
    asm volatile("mma.sync.aligned.m16n8k8.row.col.f32.tf32.tf32.f32 "
                 "{%0,%1,%2,%3}, {%4,%5,%6,%7}, {%8,%9}, {%0,%1,%2,%3};"
                 : "+f"(c[0]), "+f"(c[1]), "+f"(c[2]), "+f"(c[3])
                 : "r"(a0), "r"(a1), "r"(a2), "r"(a3), "r"(b0), "r"(b1));
}

__device__ __forceinline__ void cp_async4(unsigned dst, const float* src, bool ok) {
    int sz = ok ? 4 : 0;
    asm volatile("cp.async.ca.shared.global [%0], [%1], 4, %2;"
                 :: "r"(dst), "l"(src), "r"(sz));
}

__device__ __forceinline__ void cp_async16(unsigned dst, const void* src, bool ok) {
    int sz = ok ? 16 : 0;
    asm volatile("cp.async.cg.shared.global [%0], [%1], 16, %2;"
                 :: "r"(dst), "l"(src), "r"(sz));
}

// ---------------------------------------------------------------------------
// Weight prepack: OIHW fp32 -> tf32 uint4 fragments in exact conv order.
//   e = ((t*KSC + k)*NPAIR + p)*32 + lane, per (group, chunk) block of WCNT.
// ---------------------------------------------------------------------------
__global__ void prep_w_k(const float* __restrict__ w, uint4* __restrict__ dst,
                         int CI, int COT, int NT, int total)
{
    int e = blockIdx.x * 256 + threadIdx.x;
    if (e >= total) return;
    const int NPAIR = NT / 2;
    const int KSC = 2;
    const int WCNT = 9 * KSC * NPAIR * 32;
    const int NCH = CI / 16;

    int gch = e / WCNT, rem = e % WCNT;
    int g = gch / NCH, ch = gch % NCH;
    int lane = rem & 31;
    int q = rem >> 5;
    int p = q % NPAIR;
    int tk = q / NPAIR;
    int k = tk % KSC, t = tk / KSC;

    int coa = g * NT * 8 + 2 * p * 8 + (lane >> 2);
    int cob = coa + 8;
    int ci = ch * 16 + k * 8 + (lane & 3);

    float b0 = 0.f, b1 = 0.f, b2 = 0.f, b3 = 0.f;
    if (coa < COT) {
        b0 = w[(coa * CI + ci) * 9 + t];
        b1 = w[(coa * CI + ci + 4) * 9 + t];
    }
    if (cob < COT) {
        b2 = w[(cob * CI + ci) * 9 + t];
        b3 = w[(cob * CI + ci + 4) * 9 + t];
    }
    dst[e] = make_uint4(f2tf32(b0), f2tf32(b1), f2tf32(b2), f2tf32(b3));
}

// ---------------------------------------------------------------------------
// TF32 3x3 SAME conv + ReLU, NCHW. Inputs must be tf32-valued fp32.
//   Block 256 thr (8 warps), pixel tile 32x8, warp w owns row w.
//   Warp: 2 M-tiles (16px) x NT N-tiles (8 co). CI chunked by 16, double
//   buffered via cp.async (input 16B-vectorized + prepacked weights linear).
//   Smem tile: IPITCH=40, interior at word 4 (16B aligned), halo at 3 / 36.
//   ICH=408 => aci-stride mod 32 = 24 => conflict-free A loads.
// ---------------------------------------------------------------------------
template <int CI, int NT, int COT, int H, int W, bool ROUND>
__global__ __launch_bounds__(256, 2)
void conv3x3_tf32_v4(const float* __restrict__ in, const uint4* __restrict__ wp,
                     float* __restrict__ out)
{
    constexpr int CC  = 16;
    constexpr int NCH = CI / CC;
    constexpr int KSC = 2;
    constexpr int IPITCH = 40;
    constexpr int ICH = 408;                 // 10*40 + 8 pad
    constexpr int ISZ = CC * ICH;            // 6528 words per buffer
    constexpr int NPAIR = NT / 2;
    constexpr int WCNT = 9 * KSC * NPAIR * 32;
    constexpr int WIT = (WCNT + 255) / 256;
    constexpr int GROUPS = (COT + NT * 8 - 1) / (NT * 8);

    extern __shared__ unsigned smem_u[];
    unsigned* in_s = smem_u;                       // [2][ISZ]
    uint4*    ws   = (uint4*)(smem_u + 2 * ISZ);   // [2][WCNT]

    const int tid  = threadIdx.x;
    const int lane = tid & 31;
    const int wrp  = tid >> 5;
    const int gx0  = blockIdx.x * 32;
    const int gy0  = blockIdx.y * 8;
    const int img  = blockIdx.z / GROUPS;
    const int grp  = blockIdx.z % GROUPS;

    const float* inN = in + (size_t)img * CI * H * W;
    const unsigned in_base = (unsigned)__cvta_generic_to_shared(in_s);
    const unsigned ws_base = (unsigned)__cvta_generic_to_shared(ws);

    // ---- stage one chunk: input tile (vectorized) + weights (linear) ----
    auto fill = [&](int ch, int buf) {
        const float* base = inN + (size_t)ch * CC * H * W;
        const unsigned sbase = in_base + buf * (ISZ * 4);
        // interior: 1280 16B segments == 5 per thread exactly
#pragma unroll
        for (int j = 0; j < 5; ++j) {
            int idx = tid + j * 256;
            int ci = idx / 80;
            int rem = idx % 80;
            int r = rem >> 3, seg = rem & 7;
            int gy = gy0 + r - 1;
            bool ok = (unsigned)gy < (unsigned)H;
            const float* src = base + (size_t)ci * H * W
                             + (ok ? gy : 0) * W + gx0 + seg * 4;
            unsigned dst = sbase + (ci * ICH + r * IPITCH + 4 + seg * 4) * 4;
            cp_async16(dst, src, ok);
        }
        // halo: 320 scalar elements
#pragma unroll
        for (int j = 0; j < 2; ++j) {
            int idx = tid + j * 256;
            if (idx < CC * 20) {
                int ci = idx / 20;
                int rem = idx % 20;
                int r = rem >> 1, side = rem & 1;
                int gy = gy0 + r - 1;
                int gx = side ? gx0 + 32 : gx0 - 1;
                bool ok = ((unsigned)gy < (unsigned)H) && ((unsigned)gx < (unsigned)W);
                const float* src = base + (size_t)ci * H * W
                                 + (ok ? gy * W + gx : 0);
                unsigned dst = sbase + (ci * ICH + r * IPITCH + (side ? 36 : 3)) * 4;
                cp_async4(dst, src, ok);
            }
        }
        // weights: prepacked, linear 16B copies
        const uint4* wsrc = wp + ((size_t)grp * NCH + ch) * WCNT;
        const unsigned wdst = ws_base + buf * WCNT * 16;
#pragma unroll
        for (int j = 0; j < WIT; ++j) {
            int i = tid + j * 256;
            if (i < WCNT)
                cp_async16(wdst + i * 16, wsrc + i, true);
        }
        asm volatile("cp.async.commit_group;");
    };

    float acc[2][NT][4];
#pragma unroll
    for (int m = 0; m < 2; ++m)
#pragma unroll
        for (int n = 0; n < NT; ++n)
#pragma unroll
            for (int i = 0; i < 4; ++i) acc[m][n][i] = 0.f;

    fill(0, 0);
    asm volatile("cp.async.wait_group 0;");
    __syncthreads();

    const int arow = lane >> 2;
    const int aci  = lane & 3;

    for (int ch = 0; ch < NCH; ++ch) {
        const int buf = ch & 1;
        if (ch + 1 < NCH) fill(ch + 1, buf ^ 1);

        const unsigned* A = in_s + buf * ISZ;
        const uint4*    B = ws + buf * WCNT;
#pragma unroll
        for (int kh = 0; kh < 3; ++kh) {
#pragma unroll
            for (int kw = 0; kw < 3; ++kw) {
                const int t = kh * 3 + kw;
                const int roff = (wrp + kh) * IPITCH + kw + 3 + arow;
#pragma unroll
                for (int k = 0; k < KSC; ++k) {
                    const int ab = (k * 8 + aci) * ICH + roff;
                    unsigned a00 = A[ab];
                    unsigned a01 = A[ab + 8];
                    unsigned a02 = A[ab + 4 * ICH];
                    unsigned a03 = A[ab + 4 * ICH + 8];
                    unsigned a10 = A[ab + 16];
                    unsigned a11 = A[ab + 24];
                    unsigned a12 = A[ab + 4 * ICH + 16];
                    unsigned a13 = A[ab + 4 * ICH + 24];
                    const uint4* wb = B + (t * KSC + k) * NPAIR * 32 + lane;
#pragma unroll
                    for (int p = 0; p < NPAIR; ++p) {
                        uint4 b = wb[p * 32];
                        mma_tf32(acc[0][2 * p],     a00, a01, a02, a03, b.x, b.y);
                        mma_tf32(acc[1][2 * p],     a10, a11, a12, a13, b.x, b.y);
                        mma_tf32(acc[0][2 * p + 1], a00, a01, a02, a03, b.z, b.w);
                        mma_tf32(acc[1][2 * p + 1], a10, a11, a12, a13, b.z, b.w);
                    }
                }
            }
        }

        if (ch + 1 < NCH) {
            asm volatile("cp.async.wait_group 0;");
            __syncthreads();
        }
    }

    // ---- epilogue: ReLU (+ optional tf32 rounding) + store ----
    const int y = gy0 + wrp;
#pragma unroll
    for (int m = 0; m < 2; ++m) {
        const int x0 = gx0 + m * 16 + arow;
#pragma unroll
        for (int n = 0; n < NT; ++n) {
            const int coA = grp * NT * 8 + n * 8 + 2 * (lane & 3);
            float v0 = fmaxf(acc[m][n][0], 0.f);
            float v1 = fmaxf(acc[m][n][1], 0.f);
            float v2 = fmaxf(acc[m][n][2], 0.f);
            float v3 = fmaxf(acc[m][n][3], 0.f);
            if (ROUND) {
                v0 = round_tf32(v0); v1 = round_tf32(v1);
                v2 = round_tf32(v2); v3 = round_tf32(v3);
            }
            if (coA < COT) {
                float* p = out + ((size_t)(img * COT + coA) * H + y) * W;
                p[x0]     = v0;
                p[x0 + 8] = v2;
            }
            if (coA + 1 < COT) {
                float* p = out + ((size_t)(img * COT + coA + 1) * H + y) * W;
                p[x0]     = v1;
                p[x0 + 8] = v3;
            }
        }
    }
}

// ---------------------------------------------------------------------------
// fp32 3x3 conv + ReLU (CI=1 layers: e1, k1). Optionally round outputs tf32.
// ---------------------------------------------------------------------------
template <int CI, int COT, int PX, bool ROUND>
__global__ __launch_bounds__(256)
void conv3x3_relu_k(const float* __restrict__ in, const float* __restrict__ w,
                    float* __restrict__ out, int H, int W, int CO)
{
    constexpr int TW = 32;
    constexpr int TH = 8 * PX;
    __shared__ float st[(TH + 2) * (TW + 2)];
    __shared__ float ws[COT * CI * 9];

    const int tid = threadIdx.x;
    const int tx = tid & 31;
    const int ty = tid >> 5;

    const int groups = CO / COT;
    const int g  = blockIdx.z % groups;
    const int n  = blockIdx.z / groups;
    const int co0 = g * COT;

    for (int i = tid; i < COT * CI * 9; i += 256)
        ws[i] = w[co0 * CI * 9 + i];

    const int gx0 = blockIdx.x * TW;
    const int gy0 = blockIdx.y * TH;

    float acc[PX][COT];
#pragma unroll
    for (int p = 0; p < PX; ++p)
#pragma unroll
        for (int c = 0; c < COT; ++c) acc[p][c] = 0.f;

    const float* inN = in + (size_t)n * CI * H * W;
    const int r0 = ty * PX;

    for (int ci = 0; ci < CI; ++ci) {
        __syncthreads();
        const float* ip = inN + (size_t)ci * H * W;
        for (int i = tid; i < (TH + 2) * (TW + 2); i += 256) {
            int r = i / (TW + 2), c = i % (TW + 2);
            int gy = gy0 + r - 1, gx = gx0 + c - 1;
            st[i] = (gy >= 0 && gy < H && gx >= 0 && gx < W) ? ip[gy * W + gx] : 0.f;
        }
        __syncthreads();

        float v[PX + 2][3];
#pragma unroll
        for (int dy = 0; dy < PX + 2; ++dy)
#pragma unroll
            for (int dx = 0; dx < 3; ++dx)
                v[dy][dx] = st[(r0 + dy) * (TW + 2) + tx + dx];

        const float* wci = ws + ci * 9;
#pragma unroll
        for (int c = 0; c < COT; ++c) {
            const float* wp = wci + c * CI * 9;
#pragma unroll
            for (int kh = 0; kh < 3; ++kh)
#pragma unroll
                for (int kw = 0; kw < 3; ++kw) {
                    float wv = wp[kh * 3 + kw];
#pragma unroll
                    for (int p = 0; p < PX; ++p)
                        acc[p][c] += v[p + kh][kw] * wv;
                }
        }
    }

#pragma unroll
    for (int c = 0; c < COT; ++c) {
        float* op = out + ((size_t)(n * CO + co0 + c) * H + gy0 + r0) * W + gx0 + tx;
#pragma unroll
        for (int p = 0; p < PX; ++p) {
            float vv = fmaxf(acc[p][c], 0.f);
            if (ROUND) vv = round_tf32(vv);
            op[(size_t)p * W] = vv;
        }
    }
}

// ---------------------------------------------------------------------------
// PixelShuffle(4) + ReLU: (2,16,256,256) -> (2,1,1024,1024)
// ---------------------------------------------------------------------------
__global__ void shuffle_relu_k(const float* __restrict__ in, float* __restrict__ out)
{
    int idx = blockIdx.x * blockDim.x + threadIdx.x;
    int x = idx & 1023;
    int y = (idx >> 10) & 1023;
    int n = idx >> 20;
    int c = ((y & 3) << 2) | (x & 3);
    int hh = y >> 2, ww = x >> 2;
    float v = in[(((size_t)(n * 16 + c) * 256) + hh) * 256 + ww];
    out[idx] = v > 0.f ? v : 0.f;
}

// ---------------------------------------------------------------------------
// Per-pixel 5x5 dynamic conv + residual add.
// ---------------------------------------------------------------------------
__global__ __launch_bounds__(256)
void pixel_conv_add_k(const float* __restrict__ h, const float* __restrict__ ker,
                      float* __restrict__ out)
{
    constexpr int H = 1024, W = 1024;
    __shared__ float st[36 * 36];
    const int tid = threadIdx.x;
    const int tx = tid & 31, ty = tid >> 5;
    const int n = blockIdx.z;
    const int gx0 = blockIdx.x * 32, gy0 = blockIdx.y * 32;

    const float* hp = h + (size_t)n * H * W;
    for (int i = tid; i < 36 * 36; i += 256) {
        int r = i / 36, c = i % 36;
        int gy = gy0 + r - 2, gx = gx0 + c - 2;
        st[i] = (gy >= 0 && gy < H && gx >= 0 && gx < W) ? hp[gy * W + gx] : 0.f;
    }
    __syncthreads();

    const int r0 = ty * 4;
    const int x = gx0 + tx;
    float acc[4];
#pragma unroll
    for (int p = 0; p < 4; ++p)
        acc[p] = st[(r0 + p + 2) * 36 + tx + 2];  // residual h

#pragma unroll
    for (int kw = 0; kw < 5; ++kw)
#pragma unroll
        for (int kh = 0; kh < 5; ++kh) {
            const int j = kw * 5 + kh;
            const float* kp = ker + ((size_t)(n * 25 + j) * H + gy0 + r0) * W + x;
#pragma unroll
            for (int p = 0; p < 4; ++p) {
                float kv = kp[(size_t)p * W];
                acc[p] += st[(r0 + p + kh) * 36 + tx + kw] * kv;
            }
        }

#pragma unroll
    for (int p = 0; p < 4; ++p)
        out[((size_t)n * H + gy0 + r0 + p) * W + x] = acc[p];
}

// ---------------------------------------------------------------------------
// Launch sequence
// ---------------------------------------------------------------------------
extern "C" void kernel_launch(void* const* d_in, const int* in_sizes, int n_in,
                              void* d_out, int out_size)
{
    const float* x   = (const float*)d_in[0];
    const float* we1 = (const float*)d_in[1];
    const float* we2 = (const float*)d_in[2];
    const float* we3 = (const float*)d_in[3];
    const float* wd1 = (const float*)d_in[4];
    const float* wd2 = (const float*)d_in[5];
    const float* wk1 = (const float*)d_in[6];
    const float* wk2 = (const float*)d_in[7];
    const float* wk3 = (const float*)d_in[8];
    const float* wk4 = (const float*)d_in[9];
    float* out = (float*)d_out;

    float *bufA, *bufB, *hbuf;
    uint4* wpack;
    cudaGetSymbolAddress((void**)&bufA, g_bufA);
    cudaGetSymbolAddress((void**)&bufB, g_bufB);
    cudaGetSymbolAddress((void**)&hbuf, g_h);
    cudaGetSymbolAddress((void**)&wpack, g_wpack);

    // prepacked weight layout (uint4 offsets):
    //   e2: 0      (1152)   e3: 1152  (4608)   d1: 5760  (4608)
    //   d2: 10368  (1152)   k2: 11520 (4608)   k3: 16128 (4608)
    //   k4: 20736  (2304)
    const int O_E2 = 0, O_E3 = 1152, O_D1 = 5760, O_D2 = 10368;
    const int O_K2 = 11520, O_K3 = 16128, O_K4 = 20736;

    // smem sizes: 2*6528*4 (input) + 2*WCNT*16 (weights)
    const int sm_nt4 = 2 * 6528 * 4 + 2 * 1152 * 16;   // 89088
    const int sm_nt2 = 2 * 6528 * 4 + 2 * 576 * 16;    // 70656

    //                                CI NT COT    H     W  ROUND
    cudaFuncSetAttribute(conv3x3_tf32_v4<16, 4, 32, 256, 256, true>,
                         cudaFuncAttributeMaxDynamicSharedMemorySize, sm_nt4);
    cudaFuncSetAttribute(conv3x3_tf32_v4<32, 4, 64, 256, 256, true>,
                         cudaFuncAttributeMaxDynamicSharedMemorySize, sm_nt4);
    cudaFuncSetAttribute(conv3x3_tf32_v4<64, 4, 32, 256, 256, true>,
                         cudaFuncAttributeMaxDynamicSharedMemorySize, sm_nt4);
    cudaFuncSetAttribute(conv3x3_tf32_v4<32, 2, 16, 256, 256, false>,
                         cudaFuncAttributeMaxDynamicSharedMemorySize, sm_nt2);
    cudaFuncSetAttribute(conv3x3_tf32_v4<32, 4, 64, 1024, 1024, true>,
                         cudaFuncAttributeMaxDynamicSharedMemorySize, sm_nt4);
    cudaFuncSetAttribute(conv3x3_tf32_v4<64, 4, 32, 1024, 1024, true>,
                         cudaFuncAttributeMaxDynamicSharedMemorySize, sm_nt4);
    cudaFuncSetAttribute(conv3x3_tf32_v4<32, 4, 25, 1024, 1024, false>,
                         cudaFuncAttributeMaxDynamicSharedMemorySize, sm_nt4);

    const dim3 blk(256);

    // ---- weight prepack (cheap; part of the captured graph) ----
    prep_w_k<<<(1152 + 255) / 256, blk>>>(we2, wpack + O_E2, 16, 32, 4, 1152);
    prep_w_k<<<(4608 + 255) / 256, blk>>>(we3, wpack + O_E3, 32, 64, 4, 4608);
    prep_w_k<<<(4608 + 255) / 256, blk>>>(wd1, wpack + O_D1, 64, 32, 4, 4608);
    prep_w_k<<<(1152 + 255) / 256, blk>>>(wd2, wpack + O_D2, 32, 16, 2, 1152);
    prep_w_k<<<(4608 + 255) / 256, blk>>>(wk2, wpack + O_K2, 32, 64, 4, 4608);
    prep_w_k<<<(4608 + 255) / 256, blk>>>(wk3, wpack + O_K3, 64, 32, 4, 4608);
    prep_w_k<<<(2304 + 255) / 256, blk>>>(wk4, wpack + O_K4, 32, 25, 4, 2304);

    // ---- encoder / decoder @ 256x256 (N=2) ----
    conv3x3_relu_k<1, 16, 4, true><<<dim3(8, 8, 2), blk>>>(x, we1, bufA, 256, 256, 16);
    conv3x3_tf32_v4<16, 4, 32, 256, 256, true ><<<dim3(8, 32, 2), blk, sm_nt4>>>(bufA, wpack + O_E2, bufB);
    conv3x3_tf32_v4<32, 4, 64, 256, 256, true ><<<dim3(8, 32, 4), blk, sm_nt4>>>(bufB, wpack + O_E3, bufA);
    conv3x3_tf32_v4<64, 4, 32, 256, 256, true ><<<dim3(8, 32, 2), blk, sm_nt4>>>(bufA, wpack + O_D1, bufB);
    conv3x3_tf32_v4<32, 2, 16, 256, 256, false><<<dim3(8, 32, 2), blk, sm_nt2>>>(bufB, wpack + O_D2, bufA);

    // ---- pixel shuffle + relu -> (2,1,1024,1024), full fp32 ----
    shuffle_relu_k<<<8192, 256>>>(bufA, hbuf);

    // ---- kernel-prediction branch @ 1024x1024 ----
    conv3x3_relu_k<1, 16, 4, true><<<dim3(32, 32, 4), blk>>>(hbuf, wk1, bufB, 1024, 1024, 32);
    conv3x3_tf32_v4<32, 4, 64, 1024, 1024, true ><<<dim3(32, 128, 4), blk, sm_nt4>>>(bufB, wpack + O_K2, bufA);
    conv3x3_tf32_v4<64, 4, 32, 1024, 1024, true ><<<dim3(32, 128, 2), blk, sm_nt4>>>(bufA, wpack + O_K3, bufB);
    conv3x3_tf32_v4<32, 4, 25, 1024, 1024, false><<<dim3(32, 128, 2), blk, sm_nt4>>>(bufB, wpack + O_K4, bufA);

    // ---- per-pixel 5x5 conv + residual add (full fp32) ----
    pixel_conv_add_k<<<dim3(32, 32, 2), blk>>>(hbuf, bufA, out);
}

// round 7
// speedup vs baseline: 11.4561x; 1.7654x over previous
#include <cuda_runtime.h>
#include <cuda_fp16.h>
#include <cstddef>

// ---------------------------------------------------------------------------
// Scratch buffers (no cudaMalloc allowed).
//   Packed-half intermediates live in bufA/bufB reinterpreted as half2.
// ---------------------------------------------------------------------------
__device__ float g_bufA[134217728];   // 512 MB
__device__ float g_bufB[67108864];    // 256 MB
__device__ float g_h[2097152];        // 8 MB : shuffled image (fp32)
__device__ uint4 g_wpack[11520];      // prepacked fp16 weight fragments (180 KB)

// ---------------------------------------------------------------------------
// helpers
// ---------------------------------------------------------------------------
__device__ __forceinline__ unsigned packh(float lo, float hi) {
    __half2 h = __floats2half2_rn(lo, hi);
    return *reinterpret_cast<unsigned*>(&h);
}

__device__ __forceinline__ void mma_f16(float* c,
                                        unsigned a0, unsigned a1, unsigned a2, unsigned a3,
                                        unsigned b0, unsigned b1) {
    asm volatile("mma.sync.aligned.m16n8k16.row.col.f32.f16.f16.f32 "
                 "{%0,%1,%2,%3}, {%4,%5,%6,%7}, {%8,%9}, {%0,%1,%2,%3};"
                 : "+f"(c[0]), "+f"(c[1]), "+f"(c[2]), "+f"(c[3])
                 : "r"(a0), "r"(a1), "r"(a2), "r"(a3), "r"(b0), "r"(b1));
}

__device__ __forceinline__ void cp_async4(unsigned dst, const void* src, bool ok) {
    int sz = ok ? 4 : 0;
    asm volatile("cp.async.ca.shared.global [%0], [%1], 4, %2;"
                 :: "r"(dst), "l"(src), "r"(sz));
}

__device__ __forceinline__ void cp_async16(unsigned dst, const void* src, bool ok) {
    int sz = ok ? 16 : 0;
    asm volatile("cp.async.cg.shared.global [%0], [%1], 16, %2;"
                 :: "r"(dst), "l"(src), "r"(sz));
}

// ---------------------------------------------------------------------------
// Unified weight prepack: OIHW fp32 -> fp16 uint4 fragments, all 7 layers.
//   Per (group, chunk): WCNT = 9 * (NT/2) * 32 uint4, element
//   e = (t*NPAIR + p)*32 + lane. uint4 = {n0.b0, n0.b1, n1.b0, n1.b1}.
//   b0 holds channels (ci0, ci0+1), b1 holds (ci0+8, ci0+9).
// Layout offsets (uint4): e2:0 e3:576 d1:2880 d2:5184 k2:5760 k3:8064 k4:10368
// ---------------------------------------------------------------------------
__global__ void prep_all_k(const float* __restrict__ we2, const float* __restrict__ we3,
                           const float* __restrict__ wd1, const float* __restrict__ wd2,
                           const float* __restrict__ wk2, const float* __restrict__ wk3,
                           const float* __restrict__ wk4, uint4* __restrict__ dst)
{
    int e = blockIdx.x * 256 + threadIdx.x;
    if (e >= 11520) return;
    const float* w; int CI, COT, NT; int rem = e;
    if (rem < 576)                   { w = we2; CI = 16; COT = 32; NT = 4; }
    else if ((rem -= 576)  < 2304)   { w = we3; CI = 32; COT = 64; NT = 4; }
    else if ((rem -= 2304) < 2304)   { w = wd1; CI = 64; COT = 32; NT = 4; }
    else if ((rem -= 2304) < 576)    { w = wd2; CI = 32; COT = 16; NT = 2; }
    else if ((rem -= 576)  < 2304)   { w = wk2; CI = 32; COT = 64; NT = 4; }
    else if ((rem -= 2304) < 2304)   { w = wk3; CI = 64; COT = 32; NT = 4; }
    else       { rem -= 2304;          w = wk4; CI = 32; COT = 25; NT = 4; }

    int NPAIR = NT / 2;
    int WCNT = 9 * NPAIR * 32;
    int NCH = CI / 16;
    int gch = rem / WCNT, r2 = rem % WCNT;
    int g = gch / NCH, ch = gch % NCH;
    int lane = r2 & 31, q = r2 >> 5;
    int p = q % NPAIR, t = q / NPAIR;
    int coa = g * NT * 8 + 2 * p * 8 + (lane >> 2);
    int cob = coa + 8;
    int ci0 = ch * 16 + (lane & 3) * 2;

    auto fetch = [&](int co, int ci) -> float {
        return (co < COT) ? w[(co * CI + ci) * 9 + t] : 0.f;
    };
    uint4 v;
    v.x = packh(fetch(coa, ci0),     fetch(coa, ci0 + 1));
    v.y = packh(fetch(coa, ci0 + 8), fetch(coa, ci0 + 9));
    v.z = packh(fetch(cob, ci0),     fetch(cob, ci0 + 1));
    v.w = packh(fetch(cob, ci0 + 8), fetch(cob, ci0 + 9));
    dst[e] = v;
}

// ---------------------------------------------------------------------------
// FP16 tensor-core 3x3 SAME conv + ReLU.
//   Input: packed channel-pairs [N][CI/2][H][W] half2. Weights: prepacked.
//   Block 256 thr (8 warps), pixel tile 32x8, warp w owns row w.
//   Warp: 2 M-tiles (16px, m16n8k16) x NT N-tiles (8 co). CI chunked by 16
//   (8 channel-pairs), double buffered via cp.async.
//   Smem input: [8 cpair][10 rows][PITCH=40] half2, ICH2=408 (408%32=24 =>
//   conflict-free A loads). Interior at col 4, halo at 3/36.
//   PACKED: output as half2 channel pairs; else planar fp32 (masked by COT).
// ---------------------------------------------------------------------------
template <int CI, int NT, int COT, int H, int W, bool PACKED>
__global__ __launch_bounds__(256, 2)
void conv3x3_f16(const unsigned* __restrict__ in, const uint4* __restrict__ wp,
                 void* __restrict__ outv)
{
    constexpr int NCH = CI / 16;
    constexpr int PITCH = 40;
    constexpr int ICH2 = 408;                // half2 units per channel-pair slice
    constexpr int ISZ = 8 * ICH2;            // 3264 words per buffer
    constexpr int NPAIR = NT / 2;
    constexpr int WCNT = 9 * NPAIR * 32;     // uint4 per chunk
    constexpr int WIT = (WCNT + 255) / 256;
    constexpr int GROUPS = (COT + NT * 8 - 1) / (NT * 8);

    extern __shared__ unsigned smem_u[];
    unsigned* in_s = smem_u;                       // [2][ISZ]
    uint4*    ws   = (uint4*)(smem_u + 2 * ISZ);   // [2][WCNT]

    const int tid  = threadIdx.x;
    const int lane = tid & 31;
    const int wrp  = tid >> 5;
    const int gx0  = blockIdx.x * 32;
    const int gy0  = blockIdx.y * 8;
    const int img  = blockIdx.z / GROUPS;
    const int grp  = blockIdx.z % GROUPS;

    const unsigned in_base = (unsigned)__cvta_generic_to_shared(in_s);
    const unsigned ws_base = (unsigned)__cvta_generic_to_shared(ws);

    auto fill = [&](int ch, int buf) {
        const unsigned* base = in + ((size_t)img * (CI / 2) + ch * 8) * H * W;
        const unsigned sbase = in_base + buf * (ISZ * 4);
        // interior: 8 cpair x 10 rows x 8 segs(16B=4 half2) = 640
#pragma unroll
        for (int j = 0; j < 3; ++j) {
            int idx = tid + j * 256;
            if (idx < 640) {
                int ci = idx / 80;
                int rem = idx % 80;
                int r = rem >> 3, seg = rem & 7;
                int gy = gy0 + r - 1;
                bool ok = (unsigned)gy < (unsigned)H;
                const unsigned* src = base + (size_t)ci * H * W
                                    + (ok ? gy : 0) * W + gx0 + seg * 4;
                unsigned dst = sbase + (ci * ICH2 + r * PITCH + 4 + seg * 4) * 4;
                cp_async16(dst, src, ok);
            }
        }
        // halo: 8 cpair x 10 rows x 2 sides = 160 scalar half2
        if (tid < 160) {
            int ci = tid / 20;
            int rem = tid % 20;
            int r = rem >> 1, side = rem & 1;
            int gy = gy0 + r - 1;
            int gx = side ? gx0 + 32 : gx0 - 1;
            bool ok = ((unsigned)gy < (unsigned)H) && ((unsigned)gx < (unsigned)W);
            const unsigned* src = base + (size_t)ci * H * W + (ok ? gy * W + gx : 0);
            unsigned dst = sbase + (ci * ICH2 + r * PITCH + (side ? 36 : 3)) * 4;
            cp_async4(dst, src, ok);
        }
        // weights: linear 16B copies of prepacked fragments
        const uint4* wsrc = wp + ((size_t)grp * NCH + ch) * WCNT;
        const unsigned wdst = ws_base + buf * WCNT * 16;
#pragma unroll
        for (int j = 0; j < WIT; ++j) {
            int i = tid + j * 256;
            if (i < WCNT)
                cp_async16(wdst + i * 16, wsrc + i, true);
        }
        asm volatile("cp.async.commit_group;");
    };

    float acc[2][NT][4];
#pragma unroll
    for (int m = 0; m < 2; ++m)
#pragma unroll
        for (int n = 0; n < NT; ++n)
#pragma unroll
            for (int i = 0; i < 4; ++i) acc[m][n][i] = 0.f;

    fill(0, 0);
    asm volatile("cp.async.wait_group 0;");
    __syncthreads();

    const int arow = lane >> 2;
    const int aci  = lane & 3;

    for (int ch = 0; ch < NCH; ++ch) {
        const int buf = ch & 1;
        if (ch + 1 < NCH) fill(ch + 1, buf ^ 1);

        const unsigned* A = in_s + buf * ISZ;
        const uint4*    B = ws + buf * WCNT;
#pragma unroll
        for (int kh = 0; kh < 3; ++kh) {
#pragma unroll
            for (int kw = 0; kw < 3; ++kw) {
                const int t = kh * 3 + kw;
                const int off = (wrp + kh) * PITCH + 3 + kw + arow;
                // m16n8k16 A fragments: a0/a1 = k-pairs aci (cols x, x+8),
                // a2/a3 = k-pairs aci+4.
                unsigned a00 = A[aci * ICH2 + off];
                unsigned a01 = A[aci * ICH2 + off + 8];
                unsigned a02 = A[(aci + 4) * ICH2 + off];
                unsigned a03 = A[(aci + 4) * ICH2 + off + 8];
                unsigned a10 = A[aci * ICH2 + off + 16];
                unsigned a11 = A[aci * ICH2 + off + 24];
                unsigned a12 = A[(aci + 4) * ICH2 + off + 16];
                unsigned a13 = A[(aci + 4) * ICH2 + off + 24];
                const uint4* wb = B + t * NPAIR * 32 + lane;
#pragma unroll
                for (int p = 0; p < NPAIR; ++p) {
                    uint4 b = wb[p * 32];
                    mma_f16(acc[0][2 * p],     a00, a01, a02, a03, b.x, b.y);
                    mma_f16(acc[1][2 * p],     a10, a11, a12, a13, b.x, b.y);
                    mma_f16(acc[0][2 * p + 1], a00, a01, a02, a03, b.z, b.w);
                    mma_f16(acc[1][2 * p + 1], a10, a11, a12, a13, b.z, b.w);
                }
            }
        }

        if (ch + 1 < NCH) {
            asm volatile("cp.async.wait_group 0;");
            __syncthreads();
        }
    }

    // ---- epilogue: ReLU + store ----
    const int y = gy0 + wrp;
#pragma unroll
    for (int m = 0; m < 2; ++m) {
        const int x0 = gx0 + m * 16 + arow;
#pragma unroll
        for (int n = 0; n < NT; ++n) {
            const int coA = grp * NT * 8 + n * 8 + 2 * (lane & 3);
            float v0 = fmaxf(acc[m][n][0], 0.f);
            float v1 = fmaxf(acc[m][n][1], 0.f);
            float v2 = fmaxf(acc[m][n][2], 0.f);
            float v3 = fmaxf(acc[m][n][3], 0.f);
            if (PACKED) {
                unsigned* o = (unsigned*)outv;
                unsigned* p = o + ((size_t)(img * (COT / 2) + (coA >> 1)) * H + y) * W;
                p[x0]     = packh(v0, v1);
                p[x0 + 8] = packh(v2, v3);
            } else {
                float* o = (float*)outv;
                if (coA < COT) {
                    float* p = o + ((size_t)(img * COT + coA) * H + y) * W;
                    p[x0]     = v0;
                    p[x0 + 8] = v2;
                }
                if (coA + 1 < COT) {
                    float* p = o + ((size_t)(img * COT + coA + 1) * H + y) * W;
                    p[x0]     = v1;
                    p[x0 + 8] = v3;
                }
            }
        }
    }
}

// ---------------------------------------------------------------------------
// fp32 3x3 conv + ReLU for CI=1 layers (e1, k1); writes packed half2 pairs.
// ---------------------------------------------------------------------------
template <int COT, int PX>
__global__ __launch_bounds__(256)
void conv3x3_c1_k(const float* __restrict__ in, const float* __restrict__ w,
                  unsigned* __restrict__ out, int H, int W, int CO)
{
    constexpr int TW = 32;
    constexpr int TH = 8 * PX;
    __shared__ float st[(TH + 2) * (TW + 2)];
    __shared__ float ws[COT * 9];

    const int tid = threadIdx.x;
    const int tx = tid & 31;
    const int ty = tid >> 5;

    const int groups = CO / COT;
    const int g  = blockIdx.z % groups;
    const int n  = blockIdx.z / groups;
    const int co0 = g * COT;

    if (tid < COT * 9) ws[tid] = w[co0 * 9 + tid];

    const int gx0 = blockIdx.x * TW;
    const int gy0 = blockIdx.y * TH;

    const float* ip = in + (size_t)n * H * W;
    for (int i = tid; i < (TH + 2) * (TW + 2); i += 256) {
        int r = i / (TW + 2), c = i % (TW + 2);
        int gy = gy0 + r - 1, gx = gx0 + c - 1;
        st[i] = (gy >= 0 && gy < H && gx >= 0 && gx < W) ? ip[gy * W + gx] : 0.f;
    }
    __syncthreads();

    const int r0 = ty * PX;
    float v[PX + 2][3];
#pragma unroll
    for (int dy = 0; dy < PX + 2; ++dy)
#pragma unroll
        for (int dx = 0; dx < 3; ++dx)
            v[dy][dx] = st[(r0 + dy) * (TW + 2) + tx + dx];

    float acc[PX][COT];
#pragma unroll
    for (int p = 0; p < PX; ++p)
#pragma unroll
        for (int c = 0; c < COT; ++c) acc[p][c] = 0.f;

#pragma unroll
    for (int c = 0; c < COT; ++c) {
        const float* wp2 = ws + c * 9;
#pragma unroll
        for (int kh = 0; kh < 3; ++kh)
#pragma unroll
            for (int kw = 0; kw < 3; ++kw) {
                float wv = wp2[kh * 3 + kw];
#pragma unroll
                for (int p = 0; p < PX; ++p)
                    acc[p][c] += v[p + kh][kw] * wv;
            }
    }

#pragma unroll
    for (int c = 0; c < COT; c += 2) {
        unsigned* op = out + ((size_t)(n * (CO / 2) + (co0 + c) / 2) * H + gy0 + r0) * W
                     + gx0 + tx;
#pragma unroll
        for (int p = 0; p < PX; ++p) {
            float a = fmaxf(acc[p][c], 0.f);
            float b = fmaxf(acc[p][c + 1], 0.f);
            op[(size_t)p * W] = packh(a, b);
        }
    }
}

// ---------------------------------------------------------------------------
// PixelShuffle(4) + ReLU: planar fp32 (2,16,256,256) -> (2,1,1024,1024)
// ---------------------------------------------------------------------------
__global__ void shuffle_relu_k(const float* __restrict__ in, float* __restrict__ out)
{
    int idx = blockIdx.x * blockDim.x + threadIdx.x;
    int x = idx & 1023;
    int y = (idx >> 10) & 1023;
    int n = idx >> 20;
    int c = ((y & 3) << 2) | (x & 3);
    int hh = y >> 2, ww = x >> 2;
    float v = in[(((size_t)(n * 16 + c) * 256) + hh) * 256 + ww];
    out[idx] = v > 0.f ? v : 0.f;
}

// ---------------------------------------------------------------------------
// Per-pixel 5x5 dynamic conv + residual add (fp32).
// ---------------------------------------------------------------------------
__global__ __launch_bounds__(256)
void pixel_conv_add_k(const float* __restrict__ h, const float* __restrict__ ker,
                      float* __restrict__ out)
{
    constexpr int H = 1024, W = 1024;
    __shared__ float st[36 * 36];
    const int tid = threadIdx.x;
    const int tx = tid & 31, ty = tid >> 5;
    const int n = blockIdx.z;
    const int gx0 = blockIdx.x * 32, gy0 = blockIdx.y * 32;

    const float* hp = h + (size_t)n * H * W;
    for (int i = tid; i < 36 * 36; i += 256) {
        int r = i / 36, c = i % 36;
        int gy = gy0 + r - 2, gx = gx0 + c - 2;
        st[i] = (gy >= 0 && gy < H && gx >= 0 && gx < W) ? hp[gy * W + gx] : 0.f;
    }
    __syncthreads();

    const int r0 = ty * 4;
    const int x = gx0 + tx;
    float acc[4];
#pragma unroll
    for (int p = 0; p < 4; ++p)
        acc[p] = st[(r0 + p + 2) * 36 + tx + 2];  // residual h

#pragma unroll
    for (int kw = 0; kw < 5; ++kw)
#pragma unroll
        for (int kh = 0; kh < 5; ++kh) {
            const int j = kw * 5 + kh;
            const float* kp = ker + ((size_t)(n * 25 + j) * H + gy0 + r0) * W + x;
#pragma unroll
            for (int p = 0; p < 4; ++p) {
                float kv = kp[(size_t)p * W];
                acc[p] += st[(r0 + p + kh) * 36 + tx + kw] * kv;
            }
        }

#pragma unroll
    for (int p = 0; p < 4; ++p)
        out[((size_t)n * H + gy0 + r0 + p) * W + x] = acc[p];
}

// ---------------------------------------------------------------------------
// Launch sequence
// ---------------------------------------------------------------------------
extern "C" void kernel_launch(void* const* d_in, const int* in_sizes, int n_in,
                              void* d_out, int out_size)
{
    const float* x   = (const float*)d_in[0];
    const float* we1 = (const float*)d_in[1];
    const float* we2 = (const float*)d_in[2];
    const float* we3 = (const float*)d_in[3];
    const float* wd1 = (const float*)d_in[4];
    const float* wd2 = (const float*)d_in[5];
    const float* wk1 = (const float*)d_in[6];
    const float* wk2 = (const float*)d_in[7];
    const float* wk3 = (const float*)d_in[8];
    const float* wk4 = (const float*)d_in[9];
    float* out = (float*)d_out;

    float *bufA, *bufB, *hbuf;
    uint4* wpack;
    cudaGetSymbolAddress((void**)&bufA, g_bufA);
    cudaGetSymbolAddress((void**)&bufB, g_bufB);
    cudaGetSymbolAddress((void**)&hbuf, g_h);
    cudaGetSymbolAddress((void**)&wpack, g_wpack);
    unsigned* hA = (unsigned*)bufA;
    unsigned* hB = (unsigned*)bufB;

    // prepacked offsets (uint4)
    const int O_E2 = 0, O_E3 = 576, O_D1 = 2880, O_D2 = 5184;
    const int O_K2 = 5760, O_K3 = 8064, O_K4 = 10368;

    // smem: 2*3264*4 (input) + 2*WCNT*16 (weights)
    const int sm_nt4 = 2 * 3264 * 4 + 2 * 576 * 16;   // 44544
    const int sm_nt2 = 2 * 3264 * 4 + 2 * 288 * 16;   // 35328

    //                              CI NT COT    H     W  PACKED
    cudaFuncSetAttribute(conv3x3_f16<16, 4, 32, 256, 256, true>,
                         cudaFuncAttributeMaxDynamicSharedMemorySize, sm_nt4);
    cudaFuncSetAttribute(conv3x3_f16<32, 4, 64, 256, 256, true>,
                         cudaFuncAttributeMaxDynamicSharedMemorySize, sm_nt4);
    cudaFuncSetAttribute(conv3x3_f16<64, 4, 32, 256, 256, true>,
                         cudaFuncAttributeMaxDynamicSharedMemorySize, sm_nt4);
    cudaFuncSetAttribute(conv3x3_f16<32, 2, 16, 256, 256, false>,
                         cudaFuncAttributeMaxDynamicSharedMemorySize, sm_nt2);
    cudaFuncSetAttribute(conv3x3_f16<32, 4, 64, 1024, 1024, true>,
                         cudaFuncAttributeMaxDynamicSharedMemorySize, sm_nt4);
    cudaFuncSetAttribute(conv3x3_f16<64, 4, 32, 1024, 1024, true>,
                         cudaFuncAttributeMaxDynamicSharedMemorySize, sm_nt4);
    cudaFuncSetAttribute(conv3x3_f16<32, 4, 25, 1024, 1024, false>,
                         cudaFuncAttributeMaxDynamicSharedMemorySize, sm_nt4);

    const dim3 blk(256);

    // ---- weight prepack: one launch for all 7 layers ----
    prep_all_k<<<45, blk>>>(we2, we3, wd1, wd2, wk2, wk3, wk4, wpack);

    // ---- encoder / decoder @ 256x256 (N=2) ----
    conv3x3_c1_k<16, 4><<<dim3(8, 8, 2), blk>>>(x, we1, hA, 256, 256, 16);
    conv3x3_f16<16, 4, 32, 256, 256, true ><<<dim3(8, 32, 2), blk, sm_nt4>>>(hA, wpack + O_E2, hB);
    conv3x3_f16<32, 4, 64, 256, 256, true ><<<dim3(8, 32, 4), blk, sm_nt4>>>(hB, wpack + O_E3, hA);
    conv3x3_f16<64, 4, 32, 256, 256, true ><<<dim3(8, 32, 2), blk, sm_nt4>>>(hA, wpack + O_D1, hB);
    conv3x3_f16<32, 2, 16, 256, 256, false><<<dim3(8, 32, 2), blk, sm_nt2>>>(hB, wpack + O_D2, bufA);

    // ---- pixel shuffle + relu -> (2,1,1024,1024), fp32 ----
    shuffle_relu_k<<<8192, 256>>>(bufA, hbuf);

    // ---- kernel-prediction branch @ 1024x1024 ----
    conv3x3_c1_k<16, 4><<<dim3(32, 32, 4), blk>>>(hbuf, wk1, hB, 1024, 1024, 32);
    conv3x3_f16<32, 4, 64, 1024, 1024, true ><<<dim3(32, 128, 4), blk, sm_nt4>>>(hB, wpack + O_K2, hA);
    conv3x3_f16<64, 4, 32, 1024, 1024, true ><<<dim3(32, 128, 2), blk, sm_nt4>>>(hA, wpack + O_K3, hB);
    conv3x3_f16<32, 4, 25, 1024, 1024, false><<<dim3(32, 128, 2), blk, sm_nt4>>>(hB, wpack + O_K4, bufA);

    // ---- per-pixel 5x5 conv + residual add (fp32) ----
    pixel_conv_add_k<<<dim3(32, 32, 2), blk>>>(hbuf, bufA, out);
}

// round 8
// speedup vs baseline: 11.6502x; 1.0169x over previous
#include <cuda_runtime.h>
#include <cuda_fp16.h>
#include <cstddef>

// ---------------------------------------------------------------------------
// Scratch buffers (no cudaMalloc allowed).
// ---------------------------------------------------------------------------
__device__ float g_bufA[134217728];   // 512 MB
__device__ float g_bufB[67108864];    // 256 MB
__device__ float g_h[2097152];        // 8 MB : shuffled image (fp32)
__device__ uint4 g_wpack[11520];      // prepacked fp16 weight fragments (180 KB)

// ---------------------------------------------------------------------------
// helpers
// ---------------------------------------------------------------------------
__device__ __forceinline__ unsigned packh(float lo, float hi) {
    __half2 h = __floats2half2_rn(lo, hi);
    return *reinterpret_cast<unsigned*>(&h);
}

__device__ __forceinline__ void mma_f16(float* c,
                                        unsigned a0, unsigned a1, unsigned a2, unsigned a3,
                                        unsigned b0, unsigned b1) {
    asm volatile("mma.sync.aligned.m16n8k16.row.col.f32.f16.f16.f32 "
                 "{%0,%1,%2,%3}, {%4,%5,%6,%7}, {%8,%9}, {%0,%1,%2,%3};"
                 : "+f"(c[0]), "+f"(c[1]), "+f"(c[2]), "+f"(c[3])
                 : "r"(a0), "r"(a1), "r"(a2), "r"(a3), "r"(b0), "r"(b1));
}

__device__ __forceinline__ void cp_async4(unsigned dst, const void* src, bool ok) {
    int sz = ok ? 4 : 0;
    asm volatile("cp.async.ca.shared.global [%0], [%1], 4, %2;"
                 :: "r"(dst), "l"(src), "r"(sz));
}

__device__ __forceinline__ void cp_async16(unsigned dst, const void* src, bool ok) {
    int sz = ok ? 16 : 0;
    asm volatile("cp.async.cg.shared.global [%0], [%1], 16, %2;"
                 :: "r"(dst), "l"(src), "r"(sz));
}

// ---------------------------------------------------------------------------
// Unified weight prepack: OIHW fp32 -> fp16 uint4 fragments, all 7 layers.
//   Per (group, chunk): WCNT = 9 * (NT/2) * 32 uint4, element
//   e = (t*NPAIR + p)*32 + lane. uint4 = {n0.b0, n0.b1, n1.b0, n1.b1}.
//   b0 holds channels (ci0, ci0+1), b1 holds (ci0+8, ci0+9).
// Layout offsets (uint4): e2:0 e3:576 d1:2880 d2:5184 k2:5760 k3:8064 k4:10368
// ---------------------------------------------------------------------------
__global__ void prep_all_k(const float* __restrict__ we2, const float* __restrict__ we3,
                           const float* __restrict__ wd1, const float* __restrict__ wd2,
                           const float* __restrict__ wk2, const float* __restrict__ wk3,
                           const float* __restrict__ wk4, uint4* __restrict__ dst)
{
    int e = blockIdx.x * 256 + threadIdx.x;
    if (e >= 11520) return;
    const float* w; int CI, COT, NT; int rem = e;
    if (rem < 576)                   { w = we2; CI = 16; COT = 32; NT = 4; }
    else if ((rem -= 576)  < 2304)   { w = we3; CI = 32; COT = 64; NT = 4; }
    else if ((rem -= 2304) < 2304)   { w = wd1; CI = 64; COT = 32; NT = 4; }
    else if ((rem -= 2304) < 576)    { w = wd2; CI = 32; COT = 16; NT = 2; }
    else if ((rem -= 576)  < 2304)   { w = wk2; CI = 32; COT = 64; NT = 4; }
    else if ((rem -= 2304) < 2304)   { w = wk3; CI = 64; COT = 32; NT = 4; }
    else       { rem -= 2304;          w = wk4; CI = 32; COT = 25; NT = 4; }

    int NPAIR = NT / 2;
    int WCNT = 9 * NPAIR * 32;
    int NCH = CI / 16;
    int gch = rem / WCNT, r2 = rem % WCNT;
    int g = gch / NCH, ch = gch % NCH;
    int lane = r2 & 31, q = r2 >> 5;
    int p = q % NPAIR, t = q / NPAIR;
    int coa = g * NT * 8 + 2 * p * 8 + (lane >> 2);
    int cob = coa + 8;
    int ci0 = ch * 16 + (lane & 3) * 2;

    auto fetch = [&](int co, int ci) -> float {
        return (co < COT) ? w[(co * CI + ci) * 9 + t] : 0.f;
    };
    uint4 v;
    v.x = packh(fetch(coa, ci0),     fetch(coa, ci0 + 1));
    v.y = packh(fetch(coa, ci0 + 8), fetch(coa, ci0 + 9));
    v.z = packh(fetch(cob, ci0),     fetch(cob, ci0 + 1));
    v.w = packh(fetch(cob, ci0 + 8), fetch(cob, ci0 + 9));
    dst[e] = v;
}

// ---------------------------------------------------------------------------
// FP16 tensor-core 3x3 SAME conv + ReLU.
//   Input: packed channel-pairs [N][CI/2][H][W] half2. Weights: prepacked.
//   Block 256 thr (8 warps), pixel tile 32x8, warp w owns row w.
//   Warp: 2 M-tiles (16px, m16n8k16) x NT N-tiles (8 co). CI chunked by 16
//   (8 channel-pairs), double buffered via cp.async.
//   Smem input: [8 cpair][10 rows][PITCH=40] half2, ICH2=408 (408%32=24 =>
//   conflict-free A loads). Interior at col 4, halo at 3/36.
//   PACKED: output as half2 channel pairs; else planar fp32.
//   FUSE (k4 only, COT=25): fused per-pixel 5x5 dynamic conv + residual,
//   writing the final fp32 output directly. z never touches gmem.
// ---------------------------------------------------------------------------
template <int CI, int NT, int COT, int H, int W, bool PACKED, bool FUSE>
__global__ __launch_bounds__(256, 2)
void conv3x3_f16(const unsigned* __restrict__ in, const uint4* __restrict__ wp,
                 void* __restrict__ outv, const float* __restrict__ hres)
{
    constexpr int NCH = CI / 16;
    constexpr int PITCH = 40;
    constexpr int ICH2 = 408;                // half2 units per channel-pair slice
    constexpr int ISZ = 8 * ICH2;            // 3264 words per buffer
    constexpr int NPAIR = NT / 2;
    constexpr int WCNT = 9 * NPAIR * 32;     // uint4 per chunk
    constexpr int WIT = (WCNT + 255) / 256;
    constexpr int GROUPS = (COT + NT * 8 - 1) / (NT * 8);
    constexpr int ZP = 257;                  // z smem pitch per channel (floats)

    extern __shared__ unsigned smem_u[];
    unsigned* in_s = smem_u;                       // [2][ISZ]
    uint4*    ws   = (uint4*)(smem_u + 2 * ISZ);   // [2][WCNT]

    const int tid  = threadIdx.x;
    const int lane = tid & 31;
    const int wrp  = tid >> 5;
    const int gx0  = blockIdx.x * 32;
    const int gy0  = blockIdx.y * 8;
    const int img  = blockIdx.z / GROUPS;
    const int grp  = blockIdx.z % GROUPS;

    const unsigned in_base = (unsigned)__cvta_generic_to_shared(in_s);
    const unsigned ws_base = (unsigned)__cvta_generic_to_shared(ws);

    auto fill = [&](int ch, int buf) {
        const unsigned* base = in + ((size_t)img * (CI / 2) + ch * 8) * H * W;
        const unsigned sbase = in_base + buf * (ISZ * 4);
        // interior: 8 cpair x 10 rows x 8 segs(16B=4 half2) = 640
#pragma unroll
        for (int j = 0; j < 3; ++j) {
            int idx = tid + j * 256;
            if (idx < 640) {
                int ci = idx / 80;
                int rem = idx % 80;
                int r = rem >> 3, seg = rem & 7;
                int gy = gy0 + r - 1;
                bool ok = (unsigned)gy < (unsigned)H;
                const unsigned* src = base + (size_t)ci * H * W
                                    + (ok ? gy : 0) * W + gx0 + seg * 4;
                unsigned dst = sbase + (ci * ICH2 + r * PITCH + 4 + seg * 4) * 4;
                cp_async16(dst, src, ok);
            }
        }
        // halo: 8 cpair x 10 rows x 2 sides = 160 scalar half2
        if (tid < 160) {
            int ci = tid / 20;
            int rem = tid % 20;
            int r = rem >> 1, side = rem & 1;
            int gy = gy0 + r - 1;
            int gx = side ? gx0 + 32 : gx0 - 1;
            bool ok = ((unsigned)gy < (unsigned)H) && ((unsigned)gx < (unsigned)W);
            const unsigned* src = base + (size_t)ci * H * W + (ok ? gy * W + gx : 0);
            unsigned dst = sbase + (ci * ICH2 + r * PITCH + (side ? 36 : 3)) * 4;
            cp_async4(dst, src, ok);
        }
        // weights: linear 16B copies of prepacked fragments
        const uint4* wsrc = wp + ((size_t)grp * NCH + ch) * WCNT;
        const unsigned wdst = ws_base + buf * WCNT * 16;
#pragma unroll
        for (int j = 0; j < WIT; ++j) {
            int i = tid + j * 256;
            if (i < WCNT)
                cp_async16(wdst + i * 16, wsrc + i, true);
        }
        asm volatile("cp.async.commit_group;");
    };

    float acc[2][NT][4];
#pragma unroll
    for (int m = 0; m < 2; ++m)
#pragma unroll
        for (int n = 0; n < NT; ++n)
#pragma unroll
            for (int i = 0; i < 4; ++i) acc[m][n][i] = 0.f;

    fill(0, 0);
    asm volatile("cp.async.wait_group 0;");
    __syncthreads();

    const int arow = lane >> 2;
    const int aci  = lane & 3;

    for (int ch = 0; ch < NCH; ++ch) {
        const int buf = ch & 1;
        if (ch + 1 < NCH) fill(ch + 1, buf ^ 1);

        const unsigned* A = in_s + buf * ISZ;
        const uint4*    B = ws + buf * WCNT;
#pragma unroll
        for (int kh = 0; kh < 3; ++kh) {
#pragma unroll
            for (int kw = 0; kw < 3; ++kw) {
                const int t = kh * 3 + kw;
                const int off = (wrp + kh) * PITCH + 3 + kw + arow;
                unsigned a00 = A[aci * ICH2 + off];
                unsigned a01 = A[aci * ICH2 + off + 8];
                unsigned a02 = A[(aci + 4) * ICH2 + off];
                unsigned a03 = A[(aci + 4) * ICH2 + off + 8];
                unsigned a10 = A[aci * ICH2 + off + 16];
                unsigned a11 = A[aci * ICH2 + off + 24];
                unsigned a12 = A[(aci + 4) * ICH2 + off + 16];
                unsigned a13 = A[(aci + 4) * ICH2 + off + 24];
                const uint4* wb = B + t * NPAIR * 32 + lane;
#pragma unroll
                for (int p = 0; p < NPAIR; ++p) {
                    uint4 b = wb[p * 32];
                    mma_f16(acc[0][2 * p],     a00, a01, a02, a03, b.x, b.y);
                    mma_f16(acc[1][2 * p],     a10, a11, a12, a13, b.x, b.y);
                    mma_f16(acc[0][2 * p + 1], a00, a01, a02, a03, b.z, b.w);
                    mma_f16(acc[1][2 * p + 1], a10, a11, a12, a13, b.z, b.w);
                }
            }
        }

        if (ch + 1 < NCH) {
            asm volatile("cp.async.wait_group 0;");
            __syncthreads();
        }
    }

    if (FUSE) {
        // -------- fused per-pixel 5x5 dynamic conv + residual (k4) --------
        // Reuse staging smem (all A/B reads complete after barrier):
        //   z_s: [25][ZP] fp32 (channel c at z_s + c*ZP, inner [y*32+x])
        //   h_s: [12][36] fp32 (h tile, halo 2)
        __syncthreads();
        float* z_s = (float*)smem_u;
        float* h_s = z_s + 25 * ZP;

        const int y = wrp;
#pragma unroll
        for (int m = 0; m < 2; ++m) {
            const int xl = m * 16 + arow;
#pragma unroll
            for (int n = 0; n < NT; ++n) {
                const int coA = n * 8 + 2 * (lane & 3);
                float v0 = fmaxf(acc[m][n][0], 0.f);
                float v1 = fmaxf(acc[m][n][1], 0.f);
                float v2 = fmaxf(acc[m][n][2], 0.f);
                float v3 = fmaxf(acc[m][n][3], 0.f);
                if (coA < 25) {
                    z_s[coA * ZP + y * 32 + xl]     = v0;
                    z_s[coA * ZP + y * 32 + xl + 8] = v2;
                }
                if (coA + 1 < 25) {
                    z_s[(coA + 1) * ZP + y * 32 + xl]     = v1;
                    z_s[(coA + 1) * ZP + y * 32 + xl + 8] = v3;
                }
            }
        }
        // h tile: rows gy0-2..gy0+9, cols gx0-2..gx0+33
        const float* hp = hres + (size_t)img * H * W;
        for (int i = tid; i < 12 * 36; i += 256) {
            int r = i / 36, c = i % 36;
            int gy = gy0 + r - 2, gx = gx0 + c - 2;
            h_s[i] = ((unsigned)gy < (unsigned)H && (unsigned)gx < (unsigned)W)
                     ? hp[gy * W + gx] : 0.f;
        }
        __syncthreads();

        const int py = tid >> 5, px = tid & 31;
        float res = h_s[(py + 2) * 36 + px + 2];   // residual h
#pragma unroll
        for (int j = 0; j < 25; ++j) {
            const int kwv = j / 5, khv = j % 5;
            res += h_s[(py + khv) * 36 + px + kwv] * z_s[j * ZP + py * 32 + px];
        }
        float* o = (float*)outv;
        o[(size_t)img * H * W + (size_t)(gy0 + py) * W + gx0 + px] = res;
        return;
    }

    // ---- epilogue: ReLU + store ----
    const int y = gy0 + wrp;
#pragma unroll
    for (int m = 0; m < 2; ++m) {
        const int x0 = gx0 + m * 16 + arow;
#pragma unroll
        for (int n = 0; n < NT; ++n) {
            const int coA = grp * NT * 8 + n * 8 + 2 * (lane & 3);
            float v0 = fmaxf(acc[m][n][0], 0.f);
            float v1 = fmaxf(acc[m][n][1], 0.f);
            float v2 = fmaxf(acc[m][n][2], 0.f);
            float v3 = fmaxf(acc[m][n][3], 0.f);
            if (PACKED) {
                unsigned* o = (unsigned*)outv;
                unsigned* p = o + ((size_t)(img * (COT / 2) + (coA >> 1)) * H + y) * W;
                p[x0]     = packh(v0, v1);
                p[x0 + 8] = packh(v2, v3);
            } else {
                float* o = (float*)outv;
                if (coA < COT) {
                    float* p = o + ((size_t)(img * COT + coA) * H + y) * W;
                    p[x0]     = v0;
                    p[x0 + 8] = v2;
                }
                if (coA + 1 < COT) {
                    float* p = o + ((size_t)(img * COT + coA + 1) * H + y) * W;
                    p[x0]     = v1;
                    p[x0 + 8] = v3;
                }
            }
        }
    }
}

// ---------------------------------------------------------------------------
// fp32 3x3 conv + ReLU for CI=1 layers (e1, k1); writes packed half2 pairs.
// ---------------------------------------------------------------------------
template <int COT, int PX>
__global__ __launch_bounds__(256)
void conv3x3_c1_k(const float* __restrict__ in, const float* __restrict__ w,
                  unsigned* __restrict__ out, int H, int W, int CO)
{
    constexpr int TW = 32;
    constexpr int TH = 8 * PX;
    __shared__ float st[(TH + 2) * (TW + 2)];
    __shared__ float ws[COT * 9];

    const int tid = threadIdx.x;
    const int tx = tid & 31;
    const int ty = tid >> 5;

    const int groups = CO / COT;
    const int g  = blockIdx.z % groups;
    const int n  = blockIdx.z / groups;
    const int co0 = g * COT;

    if (tid < COT * 9) ws[tid] = w[co0 * 9 + tid];

    const int gx0 = blockIdx.x * TW;
    const int gy0 = blockIdx.y * TH;

    const float* ip = in + (size_t)n * H * W;
    for (int i = tid; i < (TH + 2) * (TW + 2); i += 256) {
        int r = i / (TW + 2), c = i % (TW + 2);
        int gy = gy0 + r - 1, gx = gx0 + c - 1;
        st[i] = (gy >= 0 && gy < H && gx >= 0 && gx < W) ? ip[gy * W + gx] : 0.f;
    }
    __syncthreads();

    const int r0 = ty * PX;
    float v[PX + 2][3];
#pragma unroll
    for (int dy = 0; dy < PX + 2; ++dy)
#pragma unroll
        for (int dx = 0; dx < 3; ++dx)
            v[dy][dx] = st[(r0 + dy) * (TW + 2) + tx + dx];

    float acc[PX][COT];
#pragma unroll
    for (int p = 0; p < PX; ++p)
#pragma unroll
        for (int c = 0; c < COT; ++c) acc[p][c] = 0.f;

#pragma unroll
    for (int c = 0; c < COT; ++c) {
        const float* wp2 = ws + c * 9;
#pragma unroll
        for (int kh = 0; kh < 3; ++kh)
#pragma unroll
            for (int kw = 0; kw < 3; ++kw) {
                float wv = wp2[kh * 3 + kw];
#pragma unroll
                for (int p = 0; p < PX; ++p)
                    acc[p][c] += v[p + kh][kw] * wv;
            }
    }

#pragma unroll
    for (int c = 0; c < COT; c += 2) {
        unsigned* op = out + ((size_t)(n * (CO / 2) + (co0 + c) / 2) * H + gy0 + r0) * W
                     + gx0 + tx;
#pragma unroll
        for (int p = 0; p < PX; ++p) {
            float a = fmaxf(acc[p][c], 0.f);
            float b = fmaxf(acc[p][c + 1], 0.f);
            op[(size_t)p * W] = packh(a, b);
        }
    }
}

// ---------------------------------------------------------------------------
// PixelShuffle(4) + ReLU: planar fp32 (2,16,256,256) -> (2,1,1024,1024)
// ---------------------------------------------------------------------------
__global__ void shuffle_relu_k(const float* __restrict__ in, float* __restrict__ out)
{
    int idx = blockIdx.x * blockDim.x + threadIdx.x;
    int x = idx & 1023;
    int y = (idx >> 10) & 1023;
    int n = idx >> 20;
    int c = ((y & 3) << 2) | (x & 3);
    int hh = y >> 2, ww = x >> 2;
    float v = in[(((size_t)(n * 16 + c) * 256) + hh) * 256 + ww];
    out[idx] = v > 0.f ? v : 0.f;
}

// ---------------------------------------------------------------------------
// Launch sequence
// ---------------------------------------------------------------------------
extern "C" void kernel_launch(void* const* d_in, const int* in_sizes, int n_in,
                              void* d_out, int out_size)
{
    const float* x   = (const float*)d_in[0];
    const float* we1 = (const float*)d_in[1];
    const float* we2 = (const float*)d_in[2];
    const float* we3 = (const float*)d_in[3];
    const float* wd1 = (const float*)d_in[4];
    const float* wd2 = (const float*)d_in[5];
    const float* wk1 = (const float*)d_in[6];
    const float* wk2 = (const float*)d_in[7];
    const float* wk3 = (const float*)d_in[8];
    const float* wk4 = (const float*)d_in[9];
    float* out = (float*)d_out;

    float *bufA, *bufB, *hbuf;
    uint4* wpack;
    cudaGetSymbolAddress((void**)&bufA, g_bufA);
    cudaGetSymbolAddress((void**)&bufB, g_bufB);
    cudaGetSymbolAddress((void**)&hbuf, g_h);
    cudaGetSymbolAddress((void**)&wpack, g_wpack);
    unsigned* hA = (unsigned*)bufA;
    unsigned* hB = (unsigned*)bufB;

    // prepacked offsets (uint4)
    const int O_E2 = 0, O_E3 = 576, O_D1 = 2880, O_D2 = 5184;
    const int O_K2 = 5760, O_K3 = 8064, O_K4 = 10368;

    // smem: 2*3264*4 (input) + 2*WCNT*16 (weights); FUSE reuse fits inside.
    const int sm_nt4 = 2 * 3264 * 4 + 2 * 576 * 16;   // 44544
    const int sm_nt2 = 2 * 3264 * 4 + 2 * 288 * 16;   // 35328

    //                              CI NT COT    H     W  PACKED FUSE
    cudaFuncSetAttribute(conv3x3_f16<16, 4, 32, 256, 256, true, false>,
                         cudaFuncAttributeMaxDynamicSharedMemorySize, sm_nt4);
    cudaFuncSetAttribute(conv3x3_f16<32, 4, 64, 256, 256, true, false>,
                         cudaFuncAttributeMaxDynamicSharedMemorySize, sm_nt4);
    cudaFuncSetAttribute(conv3x3_f16<64, 4, 32, 256, 256, true, false>,
                         cudaFuncAttributeMaxDynamicSharedMemorySize, sm_nt4);
    cudaFuncSetAttribute(conv3x3_f16<32, 2, 16, 256, 256, false, false>,
                         cudaFuncAttributeMaxDynamicSharedMemorySize, sm_nt2);
    cudaFuncSetAttribute(conv3x3_f16<32, 4, 64, 1024, 1024, true, false>,
                         cudaFuncAttributeMaxDynamicSharedMemorySize, sm_nt4);
    cudaFuncSetAttribute(conv3x3_f16<64, 4, 32, 1024, 1024, true, false>,
                         cudaFuncAttributeMaxDynamicSharedMemorySize, sm_nt4);
    cudaFuncSetAttribute(conv3x3_f16<32, 4, 25, 1024, 1024, false, true>,
                         cudaFuncAttributeMaxDynamicSharedMemorySize, sm_nt4);

    const dim3 blk(256);

    // ---- weight prepack: one launch for all 7 layers ----
    prep_all_k<<<45, blk>>>(we2, we3, wd1, wd2, wk2, wk3, wk4, wpack);

    // ---- encoder / decoder @ 256x256 (N=2) ----
    conv3x3_c1_k<16, 4><<<dim3(8, 8, 2), blk>>>(x, we1, hA, 256, 256, 16);
    conv3x3_f16<16, 4, 32, 256, 256, true,  false><<<dim3(8, 32, 2), blk, sm_nt4>>>(hA, wpack + O_E2, hB, nullptr);
    conv3x3_f16<32, 4, 64, 256, 256, true,  false><<<dim3(8, 32, 4), blk, sm_nt4>>>(hB, wpack + O_E3, hA, nullptr);
    conv3x3_f16<64, 4, 32, 256, 256, true,  false><<<dim3(8, 32, 2), blk, sm_nt4>>>(hA, wpack + O_D1, hB, nullptr);
    conv3x3_f16<32, 2, 16, 256, 256, false, false><<<dim3(8, 32, 2), blk, sm_nt2>>>(hB, wpack + O_D2, bufA, nullptr);

    // ---- pixel shuffle + relu -> (2,1,1024,1024), fp32 ----
    shuffle_relu_k<<<8192, 256>>>(bufA, hbuf);

    // ---- kernel-prediction branch @ 1024x1024 ----
    conv3x3_c1_k<16, 4><<<dim3(32, 32, 4), blk>>>(hbuf, wk1, hB, 1024, 1024, 32);
    conv3x3_f16<32, 4, 64, 1024, 1024, true,  false><<<dim3(32, 128, 4), blk, sm_nt4>>>(hB, wpack + O_K2, hA, nullptr);
    conv3x3_f16<64, 4, 32, 1024, 1024, true,  false><<<dim3(32, 128, 2), blk, sm_nt4>>>(hA, wpack + O_K3, hB, nullptr);
    // k4 fused with per-pixel 5x5 dynamic conv + residual: writes d_out directly
    conv3x3_f16<32, 4, 25, 1024, 1024, false, true ><<<dim3(32, 128, 2), blk, sm_nt4>>>(hB, wpack + O_K4, out, hbuf);
}

// round 9
// speedup vs baseline: 13.4129x; 1.1513x over previous
#include <cuda_runtime.h>
#include <cuda_fp16.h>
#include <cstddef>

// ---------------------------------------------------------------------------
// Scratch buffers (no cudaMalloc allowed).
// ---------------------------------------------------------------------------
__device__ float g_bufA[134217728];   // 512 MB
__device__ float g_bufB[67108864];    // 256 MB
__device__ float g_h[2097152];        // 8 MB : shuffled image (fp32)
__device__ uint4 g_wpack[11520];      // prepacked fp16 weight fragments (180 KB)

// ---------------------------------------------------------------------------
// helpers
// ---------------------------------------------------------------------------
__device__ __forceinline__ unsigned packh(float lo, float hi) {
    __half2 h = __floats2half2_rn(lo, hi);
    return *reinterpret_cast<unsigned*>(&h);
}

__device__ __forceinline__ void mma_f16(float* c,
                                        unsigned a0, unsigned a1, unsigned a2, unsigned a3,
                                        unsigned b0, unsigned b1) {
    asm volatile("mma.sync.aligned.m16n8k16.row.col.f32.f16.f16.f32 "
                 "{%0,%1,%2,%3}, {%4,%5,%6,%7}, {%8,%9}, {%0,%1,%2,%3};"
                 : "+f"(c[0]), "+f"(c[1]), "+f"(c[2]), "+f"(c[3])
                 : "r"(a0), "r"(a1), "r"(a2), "r"(a3), "r"(b0), "r"(b1));
}

__device__ __forceinline__ void cp_async4(unsigned dst, const void* src, bool ok) {
    int sz = ok ? 4 : 0;
    asm volatile("cp.async.ca.shared.global [%0], [%1], 4, %2;"
                 :: "r"(dst), "l"(src), "r"(sz));
}

__device__ __forceinline__ void cp_async16(unsigned dst, const void* src, bool ok) {
    int sz = ok ? 16 : 0;
    asm volatile("cp.async.cg.shared.global [%0], [%1], 16, %2;"
                 :: "r"(dst), "l"(src), "r"(sz));
}

// ---------------------------------------------------------------------------
// Unified weight prepack: OIHW fp32 -> fp16 uint4 fragments, all 7 layers.
//   uint4 e = (t*NPAIR + p)*32 + lane per (group, chunk) block of WCNT.
// Offsets (uint4): e2:0 e3:576 d1:2880 d2:5184 k2:5760 k3:8064 k4:10368
// ---------------------------------------------------------------------------
__global__ void prep_all_k(const float* __restrict__ we2, const float* __restrict__ we3,
                           const float* __restrict__ wd1, const float* __restrict__ wd2,
                           const float* __restrict__ wk2, const float* __restrict__ wk3,
                           const float* __restrict__ wk4, uint4* __restrict__ dst)
{
    int e = blockIdx.x * 256 + threadIdx.x;
    if (e >= 11520) return;
    const float* w; int CI, COT, NT; int rem = e;
    if (rem < 576)                   { w = we2; CI = 16; COT = 32; NT = 4; }
    else if ((rem -= 576)  < 2304)   { w = we3; CI = 32; COT = 64; NT = 4; }
    else if ((rem -= 2304) < 2304)   { w = wd1; CI = 64; COT = 32; NT = 4; }
    else if ((rem -= 2304) < 576)    { w = wd2; CI = 32; COT = 16; NT = 2; }
    else if ((rem -= 576)  < 2304)   { w = wk2; CI = 32; COT = 64; NT = 4; }
    else if ((rem -= 2304) < 2304)   { w = wk3; CI = 64; COT = 32; NT = 4; }
    else       { rem -= 2304;          w = wk4; CI = 32; COT = 25; NT = 4; }

    int NPAIR = NT / 2;
    int WCNT = 9 * NPAIR * 32;
    int NCH = CI / 16;
    int gch = rem / WCNT, r2 = rem % WCNT;
    int g = gch / NCH, ch = gch % NCH;
    int lane = r2 & 31, q = r2 >> 5;
    int p = q % NPAIR, t = q / NPAIR;
    int coa = g * NT * 8 + 2 * p * 8 + (lane >> 2);
    int cob = coa + 8;
    int ci0 = ch * 16 + (lane & 3) * 2;

    auto fetch = [&](int co, int ci) -> float {
        return (co < COT) ? w[(co * CI + ci) * 9 + t] : 0.f;
    };
    uint4 v;
    v.x = packh(fetch(coa, ci0),     fetch(coa, ci0 + 1));
    v.y = packh(fetch(coa, ci0 + 8), fetch(coa, ci0 + 9));
    v.z = packh(fetch(cob, ci0),     fetch(cob, ci0 + 1));
    v.w = packh(fetch(cob, ci0 + 8), fetch(cob, ci0 + 9));
    dst[e] = v;
}

// ---------------------------------------------------------------------------
// FP16 tensor-core 3x3 SAME conv + ReLU.  Pixel tile 32(x) x 16(y).
//   Block 256 thr (8 warps); warp w computes output rows w and w+8.
//   Per warp: 4 M-tiles (2 rows x 2 col-halves) x NT N-tiles (8 co).
//   Input: packed channel-pairs [N][CI/2][H][W] half2, CI chunked by 16
//   (8 cpair), double buffered via cp.async; prepacked weights linear.
//   Smem input: [8 cpair][18 rows][PITCH=40] half2, ICH2=728 (728%32=24 =>
//   conflict-free A loads). Interior at col 4, halo at 3/36.
//   PACKED: output half2 channel pairs; else planar fp32 (masked).
//   FUSE (k4): fused per-pixel 5x5 dynamic conv + residual -> final output.
// ---------------------------------------------------------------------------
template <int CI, int NT, int COT, int H, int W, bool PACKED, bool FUSE>
__global__ __launch_bounds__(256, 2)
void conv3x3_f16(const unsigned* __restrict__ in, const uint4* __restrict__ wp,
                 void* __restrict__ outv, const float* __restrict__ hres)
{
    constexpr int NCH = CI / 16;
    constexpr int PITCH = 40;
    constexpr int ICH2 = 728;                // 18*40 + 8 pad (half2 units)
    constexpr int ISZ = 8 * ICH2;            // 5824 words per buffer
    constexpr int NPAIR = NT / 2;
    constexpr int WCNT = 9 * NPAIR * 32;     // uint4 per chunk
    constexpr int WIT = (WCNT + 255) / 256;
    constexpr int GROUPS = (COT + NT * 8 - 1) / (NT * 8);
    constexpr int ZP = 513;                  // z smem pitch (16*32+1 floats)

    extern __shared__ unsigned smem_u[];
    unsigned* in_s = smem_u;                       // [2][ISZ]
    uint4*    ws   = (uint4*)(smem_u + 2 * ISZ);   // [2][WCNT]

    const int tid  = threadIdx.x;
    const int lane = tid & 31;
    const int wrp  = tid >> 5;
    const int gx0  = blockIdx.x * 32;
    const int gy0  = blockIdx.y * 16;
    const int img  = blockIdx.z / GROUPS;
    const int grp  = blockIdx.z % GROUPS;

    const unsigned in_base = (unsigned)__cvta_generic_to_shared(in_s);
    const unsigned ws_base = (unsigned)__cvta_generic_to_shared(ws);

    auto fill = [&](int ch, int buf) {
        const unsigned* base = in + ((size_t)img * (CI / 2) + ch * 8) * H * W;
        const unsigned sbase = in_base + buf * (ISZ * 4);
        // interior: 8 cpair x 18 rows x 8 segs(16B) = 1152
#pragma unroll
        for (int j = 0; j < 5; ++j) {
            int idx = tid + j * 256;
            if (idx < 1152) {
                int ci = idx / 144;
                int rem = idx % 144;
                int r = rem >> 3, seg = rem & 7;
                int gy = gy0 + r - 1;
                bool ok = (unsigned)gy < (unsigned)H;
                const unsigned* src = base + (size_t)ci * H * W
                                    + (ok ? gy : 0) * W + gx0 + seg * 4;
                unsigned dst = sbase + (ci * ICH2 + r * PITCH + 4 + seg * 4) * 4;
                cp_async16(dst, src, ok);
            }
        }
        // halo: 8 cpair x 18 rows x 2 sides = 288 scalar half2
#pragma unroll
        for (int j = 0; j < 2; ++j) {
            int idx = tid + j * 256;
            if (idx < 288) {
                int ci = idx / 36;
                int rem = idx % 36;
                int r = rem >> 1, side = rem & 1;
                int gy = gy0 + r - 1;
                int gx = side ? gx0 + 32 : gx0 - 1;
                bool ok = ((unsigned)gy < (unsigned)H) && ((unsigned)gx < (unsigned)W);
                const unsigned* src = base + (size_t)ci * H * W + (ok ? gy * W + gx : 0);
                unsigned dst = sbase + (ci * ICH2 + r * PITCH + (side ? 36 : 3)) * 4;
                cp_async4(dst, src, ok);
            }
        }
        // weights: linear 16B copies of prepacked fragments
        const uint4* wsrc = wp + ((size_t)grp * NCH + ch) * WCNT;
        const unsigned wdst = ws_base + buf * WCNT * 16;
#pragma unroll
        for (int j = 0; j < WIT; ++j) {
            int i = tid + j * 256;
            if (i < WCNT)
                cp_async16(wdst + i * 16, wsrc + i, true);
        }
        asm volatile("cp.async.commit_group;");
    };

    float acc[2][2][NT][4];   // [row-half][col-half][ntile][frag]
#pragma unroll
    for (int mr = 0; mr < 2; ++mr)
#pragma unroll
        for (int m = 0; m < 2; ++m)
#pragma unroll
            for (int n = 0; n < NT; ++n)
#pragma unroll
                for (int i = 0; i < 4; ++i) acc[mr][m][n][i] = 0.f;

    fill(0, 0);
    asm volatile("cp.async.wait_group 0;");
    __syncthreads();

    const int arow = lane >> 2;
    const int aci  = lane & 3;

    for (int ch = 0; ch < NCH; ++ch) {
        const int buf = ch & 1;
        if (ch + 1 < NCH) fill(ch + 1, buf ^ 1);

        const unsigned* A = in_s + buf * ISZ;
        const uint4*    B = ws + buf * WCNT;
#pragma unroll
        for (int kh = 0; kh < 3; ++kh) {
#pragma unroll
            for (int kw = 0; kw < 3; ++kw) {
                const int t = kh * 3 + kw;
                const uint4* wb = B + t * NPAIR * 32 + lane;
#pragma unroll
                for (int mr = 0; mr < 2; ++mr) {
                    const int off = (wrp + mr * 8 + kh) * PITCH + 3 + kw + arow;
                    unsigned a00 = A[aci * ICH2 + off];
                    unsigned a01 = A[aci * ICH2 + off + 8];
                    unsigned a02 = A[(aci + 4) * ICH2 + off];
                    unsigned a03 = A[(aci + 4) * ICH2 + off + 8];
                    unsigned a10 = A[aci * ICH2 + off + 16];
                    unsigned a11 = A[aci * ICH2 + off + 24];
                    unsigned a12 = A[(aci + 4) * ICH2 + off + 16];
                    unsigned a13 = A[(aci + 4) * ICH2 + off + 24];
#pragma unroll
                    for (int p = 0; p < NPAIR; ++p) {
                        uint4 b = wb[p * 32];
                        mma_f16(acc[mr][0][2 * p],     a00, a01, a02, a03, b.x, b.y);
                        mma_f16(acc[mr][1][2 * p],     a10, a11, a12, a13, b.x, b.y);
                        mma_f16(acc[mr][0][2 * p + 1], a00, a01, a02, a03, b.z, b.w);
                        mma_f16(acc[mr][1][2 * p + 1], a10, a11, a12, a13, b.z, b.w);
                    }
                }
            }
        }

        if (ch + 1 < NCH) {
            asm volatile("cp.async.wait_group 0;");
            __syncthreads();
        }
    }

    if (FUSE) {
        // -------- fused per-pixel 5x5 dynamic conv + residual (k4) --------
        // Reuse staging smem after barrier:
        //   z_s: [25][ZP] fp32 (channel c, inner [y*32+x], y in 0..15)
        //   h_s: [20][36] fp32 (h tile, halo 2)
        __syncthreads();
        float* z_s = (float*)smem_u;
        float* h_s = z_s + 25 * ZP;

#pragma unroll
        for (int mr = 0; mr < 2; ++mr) {
            const int y = wrp + mr * 8;
#pragma unroll
            for (int m = 0; m < 2; ++m) {
                const int xl = m * 16 + arow;
#pragma unroll
                for (int n = 0; n < NT; ++n) {
                    const int coA = n * 8 + 2 * (lane & 3);
                    float v0 = fmaxf(acc[mr][m][n][0], 0.f);
                    float v1 = fmaxf(acc[mr][m][n][1], 0.f);
                    float v2 = fmaxf(acc[mr][m][n][2], 0.f);
                    float v3 = fmaxf(acc[mr][m][n][3], 0.f);
                    if (coA < 25) {
                        z_s[coA * ZP + y * 32 + xl]     = v0;
                        z_s[coA * ZP + y * 32 + xl + 8] = v2;
                    }
                    if (coA + 1 < 25) {
                        z_s[(coA + 1) * ZP + y * 32 + xl]     = v1;
                        z_s[(coA + 1) * ZP + y * 32 + xl + 8] = v3;
                    }
                }
            }
        }
        // h tile: rows gy0-2..gy0+17, cols gx0-2..gx0+33 (20 x 36)
        const float* hp = hres + (size_t)img * H * W;
        for (int i = tid; i < 20 * 36; i += 256) {
            int r = i / 36, c = i % 36;
            int gy = gy0 + r - 2, gx = gx0 + c - 2;
            h_s[i] = ((unsigned)gy < (unsigned)H && (unsigned)gx < (unsigned)W)
                     ? hp[gy * W + gx] : 0.f;
        }
        __syncthreads();

        const int py = tid >> 5, px = tid & 31;
        float* o = (float*)outv;
#pragma unroll
        for (int mr = 0; mr < 2; ++mr) {
            const int yy = py + mr * 8;
            float res = h_s[(yy + 2) * 36 + px + 2];   // residual h
#pragma unroll
            for (int j = 0; j < 25; ++j) {
                const int kwv = j / 5, khv = j % 5;
                res += h_s[(yy + khv) * 36 + px + kwv] * z_s[j * ZP + yy * 32 + px];
            }
            o[(size_t)img * H * W + (size_t)(gy0 + yy) * W + gx0 + px] = res;
        }
        return;
    }

    // ---- epilogue: ReLU + store ----
#pragma unroll
    for (int mr = 0; mr < 2; ++mr) {
        const int y = gy0 + wrp + mr * 8;
#pragma unroll
        for (int m = 0; m < 2; ++m) {
            const int x0 = gx0 + m * 16 + arow;
#pragma unroll
            for (int n = 0; n < NT; ++n) {
                const int coA = grp * NT * 8 + n * 8 + 2 * (lane & 3);
                float v0 = fmaxf(acc[mr][m][n][0], 0.f);
                float v1 = fmaxf(acc[mr][m][n][1], 0.f);
                float v2 = fmaxf(acc[mr][m][n][2], 0.f);
                float v3 = fmaxf(acc[mr][m][n][3], 0.f);
                if (PACKED) {
                    unsigned* o = (unsigned*)outv;
                    unsigned* p = o + ((size_t)(img * (COT / 2) + (coA >> 1)) * H + y) * W;
                    p[x0]     = packh(v0, v1);
                    p[x0 + 8] = packh(v2, v3);
                } else {
                    float* o = (float*)outv;
                    if (coA < COT) {
                        float* p = o + ((size_t)(img * COT + coA) * H + y) * W;
                        p[x0]     = v0;
                        p[x0 + 8] = v2;
                    }
                    if (coA + 1 < COT) {
                        float* p = o + ((size_t)(img * COT + coA + 1) * H + y) * W;
                        p[x0]     = v1;
                        p[x0 + 8] = v3;
                    }
                }
            }
        }
    }
}

// ---------------------------------------------------------------------------
// fp32 3x3 conv + ReLU for CI=1 layers (e1, k1); writes packed half2 pairs.
// ---------------------------------------------------------------------------
template <int COT, int PX>
__global__ __launch_bounds__(256)
void conv3x3_c1_k(const float* __restrict__ in, const float* __restrict__ w,
                  unsigned* __restrict__ out, int H, int W, int CO)
{
    constexpr int TW = 32;
    constexpr int TH = 8 * PX;
    __shared__ float st[(TH + 2) * (TW + 2)];
    __shared__ float ws[COT * 9];

    const int tid = threadIdx.x;
    const int tx = tid & 31;
    const int ty = tid >> 5;

    const int groups = CO / COT;
    const int g  = blockIdx.z % groups;
    const int n  = blockIdx.z / groups;
    const int co0 = g * COT;

    if (tid < COT * 9) ws[tid] = w[co0 * 9 + tid];

    const int gx0 = blockIdx.x * TW;
    const int gy0 = blockIdx.y * TH;

    const float* ip = in + (size_t)n * H * W;
    for (int i = tid; i < (TH + 2) * (TW + 2); i += 256) {
        int r = i / (TW + 2), c = i % (TW + 2);
        int gy = gy0 + r - 1, gx = gx0 + c - 1;
        st[i] = (gy >= 0 && gy < H && gx >= 0 && gx < W) ? ip[gy * W + gx] : 0.f;
    }
    __syncthreads();

    const int r0 = ty * PX;
    float v[PX + 2][3];
#pragma unroll
    for (int dy = 0; dy < PX + 2; ++dy)
#pragma unroll
        for (int dx = 0; dx < 3; ++dx)
            v[dy][dx] = st[(r0 + dy) * (TW + 2) + tx + dx];

    float acc[PX][COT];
#pragma unroll
    for (int p = 0; p < PX; ++p)
#pragma unroll
        for (int c = 0; c < COT; ++c) acc[p][c] = 0.f;

#pragma unroll
    for (int c = 0; c < COT; ++c) {
        const float* wp2 = ws + c * 9;
#pragma unroll
        for (int kh = 0; kh < 3; ++kh)
#pragma unroll
            for (int kw = 0; kw < 3; ++kw) {
                float wv = wp2[kh * 3 + kw];
#pragma unroll
                for (int p = 0; p < PX; ++p)
                    acc[p][c] += v[p + kh][kw] * wv;
            }
    }

#pragma unroll
    for (int c = 0; c < COT; c += 2) {
        unsigned* op = out + ((size_t)(n * (CO / 2) + (co0 + c) / 2) * H + gy0 + r0) * W
                     + gx0 + tx;
#pragma unroll
        for (int p = 0; p < PX; ++p) {
            float a = fmaxf(acc[p][c], 0.f);
            float b = fmaxf(acc[p][c + 1], 0.f);
            op[(size_t)p * W] = packh(a, b);
        }
    }
}

// ---------------------------------------------------------------------------
// PixelShuffle(4) + ReLU: planar fp32 (2,16,256,256) -> (2,1,1024,1024)
// ---------------------------------------------------------------------------
__global__ void shuffle_relu_k(const float* __restrict__ in, float* __restrict__ out)
{
    int idx = blockIdx.x * blockDim.x + threadIdx.x;
    int x = idx & 1023;
    int y = (idx >> 10) & 1023;
    int n = idx >> 20;
    int c = ((y & 3) << 2) | (x & 3);
    int hh = y >> 2, ww = x >> 2;
    float v = in[(((size_t)(n * 16 + c) * 256) + hh) * 256 + ww];
    out[idx] = v > 0.f ? v : 0.f;
}

// ---------------------------------------------------------------------------
// Launch sequence
// ---------------------------------------------------------------------------
extern "C" void kernel_launch(void* const* d_in, const int* in_sizes, int n_in,
                              void* d_out, int out_size)
{
    const float* x   = (const float*)d_in[0];
    const float* we1 = (const float*)d_in[1];
    const float* we2 = (const float*)d_in[2];
    const float* we3 = (const float*)d_in[3];
    const float* wd1 = (const float*)d_in[4];
    const float* wd2 = (const float*)d_in[5];
    const float* wk1 = (const float*)d_in[6];
    const float* wk2 = (const float*)d_in[7];
    const float* wk3 = (const float*)d_in[8];
    const float* wk4 = (const float*)d_in[9];
    float* out = (float*)d_out;

    float *bufA, *bufB, *hbuf;
    uint4* wpack;
    cudaGetSymbolAddress((void**)&bufA, g_bufA);
    cudaGetSymbolAddress((void**)&bufB, g_bufB);
    cudaGetSymbolAddress((void**)&hbuf, g_h);
    cudaGetSymbolAddress((void**)&wpack, g_wpack);
    unsigned* hA = (unsigned*)bufA;
    unsigned* hB = (unsigned*)bufB;

    // prepacked offsets (uint4)
    const int O_E2 = 0, O_E3 = 576, O_D1 = 2880, O_D2 = 5184;
    const int O_K2 = 5760, O_K3 = 8064, O_K4 = 10368;

    // smem: 2*5824*4 (input) + 2*WCNT*16 (weights)
    const int sm_nt4 = 2 * 5824 * 4 + 2 * 576 * 16;   // 65024
    const int sm_nt2 = 2 * 5824 * 4 + 2 * 288 * 16;   // 55808

    //                              CI NT COT    H     W  PACKED FUSE
    cudaFuncSetAttribute(conv3x3_f16<16, 4, 32, 256, 256, true, false>,
                         cudaFuncAttributeMaxDynamicSharedMemorySize, sm_nt4);
    cudaFuncSetAttribute(conv3x3_f16<32, 4, 64, 256, 256, true, false>,
                         cudaFuncAttributeMaxDynamicSharedMemorySize, sm_nt4);
    cudaFuncSetAttribute(conv3x3_f16<64, 4, 32, 256, 256, true, false>,
                         cudaFuncAttributeMaxDynamicSharedMemorySize, sm_nt4);
    cudaFuncSetAttribute(conv3x3_f16<32, 2, 16, 256, 256, false, false>,
                         cudaFuncAttributeMaxDynamicSharedMemorySize, sm_nt2);
    cudaFuncSetAttribute(conv3x3_f16<32, 4, 64, 1024, 1024, true, false>,
                         cudaFuncAttributeMaxDynamicSharedMemorySize, sm_nt4);
    cudaFuncSetAttribute(conv3x3_f16<64, 4, 32, 1024, 1024, true, false>,
                         cudaFuncAttributeMaxDynamicSharedMemorySize, sm_nt4);
    cudaFuncSetAttribute(conv3x3_f16<32, 4, 25, 1024, 1024, false, true>,
                         cudaFuncAttributeMaxDynamicSharedMemorySize, sm_nt4);

    const dim3 blk(256);

    // ---- weight prepack: one launch for all 7 layers ----
    prep_all_k<<<45, blk>>>(we2, we3, wd1, wd2, wk2, wk3, wk4, wpack);

    // ---- encoder / decoder @ 256x256 (N=2), 32x16 tiles ----
    conv3x3_c1_k<16, 4><<<dim3(8, 8, 2), blk>>>(x, we1, hA, 256, 256, 16);
    conv3x3_f16<16, 4, 32, 256, 256, true,  false><<<dim3(8, 16, 2), blk, sm_nt4>>>(hA, wpack + O_E2, hB, nullptr);
    conv3x3_f16<32, 4, 64, 256, 256, true,  false><<<dim3(8, 16, 4), blk, sm_nt4>>>(hB, wpack + O_E3, hA, nullptr);
    conv3x3_f16<64, 4, 32, 256, 256, true,  false><<<dim3(8, 16, 2), blk, sm_nt4>>>(hA, wpack + O_D1, hB, nullptr);
    conv3x3_f16<32, 2, 16, 256, 256, false, false><<<dim3(8, 16, 2), blk, sm_nt2>>>(hB, wpack + O_D2, bufA, nullptr);

    // ---- pixel shuffle + relu -> (2,1,1024,1024), fp32 ----
    shuffle_relu_k<<<8192, 256>>>(bufA, hbuf);

    // ---- kernel-prediction branch @ 1024x1024, 32x16 tiles ----
    conv3x3_c1_k<16, 4><<<dim3(32, 32, 4), blk>>>(hbuf, wk1, hB, 1024, 1024, 32);
    conv3x3_f16<32, 4, 64, 1024, 1024, true,  false><<<dim3(32, 64, 4), blk, sm_nt4>>>(hB, wpack + O_K2, hA, nullptr);
    conv3x3_f16<64, 4, 32, 1024, 1024, true,  false><<<dim3(32, 64, 2), blk, sm_nt4>>>(hA, wpack + O_K3, hB, nullptr);
    // k4 fused with per-pixel 5x5 dynamic conv + residual: writes d_out directly
    conv3x3_f16<32, 4, 25, 1024, 1024, false, true ><<<dim3(32, 64, 2), blk, sm_nt4>>>(hB, wpack + O_K4, out, hbuf);
}